// round 1
// baseline (speedup 1.0000x reference)
#include <cuda_runtime.h>
#include <math.h>
#include <stdint.h>

// Scratch for intermediate t = silu(gate*mask) * (up*mask): [M=8192, I=14336] fp32.
// Static __device__ array (no allocations allowed in kernel_launch).
static __device__ float g_t[117440512ull]; // 8192 * 14336 floats = 470 MB

// ---------------------------------------------------------------------------
// Kernel 1: fused up/gate projection + mask + silu epilogue.
//   up   = x @ w_up^T    [M, I]
//   gate = x @ w_gate^T  [M, I]
//   t    = (|up*avg|>=0.5) ? silu(gate)*up : 0
// Tiling: BM=128 (tokens) x BN=64 (neurons) x BK=16, 256 threads,
// per-thread 8x4 outputs with TWO accumulators (up & gate) sharing the A frag.
// ---------------------------------------------------------------------------
__global__ __launch_bounds__(256)
void fused_upgate_kernel(const float* __restrict__ x,
                         const float* __restrict__ wg,
                         const float* __restrict__ wu,
                         const float* __restrict__ avg,
                         int M, int H, int I)
{
    constexpr int BM = 128, BN = 64, BK = 16, TM = 8, TN = 4;
    constexpr int AST = BM + 4;  // padded stride (bank-conflict relief)
    constexpr int BST = BN + 4;

    __shared__ float As[2][BK][AST];
    __shared__ float Bu[2][BK][BST];
    __shared__ float Bg[2][BK][BST];

    const int bn  = blockIdx.x * BN;
    const int bm  = blockIdx.y * BM;
    const int tid = threadIdx.x;
    const int tx  = tid & 15;       // N direction (16)
    const int ty  = tid >> 4;       // M direction (16)
    const int row0 = ty * TM;
    const int col0 = tx * TN;

    // Global->shared load mapping: each thread loads float4s along K.
    const int lr = tid >> 2;        // 0..63
    const int lk = (tid & 3) * 4;   // 0,4,8,12

    const float* pa0 = x  + (size_t)(bm + lr)      * H + lk;
    const float* pa1 = x  + (size_t)(bm + lr + 64) * H + lk;
    const float* pbu = wu + (size_t)(bn + lr)      * H + lk;
    const float* pbg = wg + (size_t)(bn + lr)      * H + lk;

    float accU[TM][TN] = {};
    float accG[TM][TN] = {};

    const int ktiles = H / BK;

    // Preload tile 0
    {
        float4 a0 = *(const float4*)pa0;
        float4 a1 = *(const float4*)pa1;
        float4 b0 = *(const float4*)pbu;
        float4 b1 = *(const float4*)pbg;
        float av0[4] = {a0.x, a0.y, a0.z, a0.w};
        float av1[4] = {a1.x, a1.y, a1.z, a1.w};
        float bv0[4] = {b0.x, b0.y, b0.z, b0.w};
        float bv1[4] = {b1.x, b1.y, b1.z, b1.w};
#pragma unroll
        for (int e = 0; e < 4; e++) {
            As[0][lk + e][lr]      = av0[e];
            As[0][lk + e][lr + 64] = av1[e];
            Bu[0][lk + e][lr]      = bv0[e];
            Bg[0][lk + e][lr]      = bv1[e];
        }
    }
    __syncthreads();

    for (int kt = 0; kt < ktiles; ++kt) {
        const int cur = kt & 1;
        const int nxt = cur ^ 1;

        // Prefetch next tile into registers (latency hidden behind compute)
        float4 na0, na1, nbu, nbg;
        const bool more = (kt + 1 < ktiles);
        if (more) {
            const int off = (kt + 1) * BK;
            na0 = *(const float4*)(pa0 + off);
            na1 = *(const float4*)(pa1 + off);
            nbu = *(const float4*)(pbu + off);
            nbg = *(const float4*)(pbg + off);
        }

#pragma unroll
        for (int k = 0; k < BK; k++) {
            float af[TM], uf[TN], gf[TN];
#pragma unroll
            for (int i = 0; i < TM; i++) af[i] = As[cur][k][row0 + i];
#pragma unroll
            for (int j = 0; j < TN; j++) {
                uf[j] = Bu[cur][k][col0 + j];
                gf[j] = Bg[cur][k][col0 + j];
            }
#pragma unroll
            for (int i = 0; i < TM; i++)
#pragma unroll
                for (int j = 0; j < TN; j++) {
                    accU[i][j] = fmaf(af[i], uf[j], accU[i][j]);
                    accG[i][j] = fmaf(af[i], gf[j], accG[i][j]);
                }
        }

        if (more) {
            float av0[4] = {na0.x, na0.y, na0.z, na0.w};
            float av1[4] = {na1.x, na1.y, na1.z, na1.w};
            float bv0[4] = {nbu.x, nbu.y, nbu.z, nbu.w};
            float bv1[4] = {nbg.x, nbg.y, nbg.z, nbg.w};
#pragma unroll
            for (int e = 0; e < 4; e++) {
                As[nxt][lk + e][lr]      = av0[e];
                As[nxt][lk + e][lr + 64] = av1[e];
                Bu[nxt][lk + e][lr]      = bv0[e];
                Bg[nxt][lk + e][lr]      = bv1[e];
            }
        }
        __syncthreads();
    }

    // Epilogue: mask + silu, write t
#pragma unroll
    for (int j = 0; j < TN; j++) {
        const int col = bn + col0 + j;
        const float a = avg[col];
#pragma unroll
        for (int i = 0; i < TM; i++) {
            const float up = accU[i][j];
            const float g  = accG[i][j];
            float v = 0.0f;
            if (fabsf(up * a) >= 0.5f) {
                v = (g / (1.0f + expf(-g))) * up;  // silu(g) * up
            }
            g_t[(size_t)(bm + row0 + i) * I + col] = v;
        }
    }
}

// ---------------------------------------------------------------------------
// Kernel 2: down projection.  out[M,H] = t[M,I] @ w_down[H,I]^T
// Tiling: BM=128 x BN=128 x BK=16, 256 threads, per-thread 8x8.
// ---------------------------------------------------------------------------
__global__ __launch_bounds__(256)
void down_kernel(const float* __restrict__ wd,
                 float* __restrict__ out,
                 int M, int H, int I)
{
    constexpr int BM = 128, BN = 128, BK = 16, TM = 8, TN = 8;
    constexpr int AST = BM + 4;

    __shared__ float As[2][BK][AST];
    __shared__ float Bs[2][BK][AST];

    const int bn  = blockIdx.x * BN;
    const int bm  = blockIdx.y * BM;
    const int tid = threadIdx.x;
    const int tx  = tid & 15;
    const int ty  = tid >> 4;
    const int row0 = ty * TM;
    const int col0 = tx * TN;

    const int lr = tid >> 2;        // 0..63
    const int lk = (tid & 3) * 4;   // 0,4,8,12

    const float* pa0 = g_t + (size_t)(bm + lr)      * I + lk;
    const float* pa1 = g_t + (size_t)(bm + lr + 64) * I + lk;
    const float* pb0 = wd  + (size_t)(bn + lr)      * I + lk;
    const float* pb1 = wd  + (size_t)(bn + lr + 64) * I + lk;

    float acc[TM][TN] = {};

    const int ktiles = I / BK;

    {
        float4 a0 = *(const float4*)pa0;
        float4 a1 = *(const float4*)pa1;
        float4 b0 = *(const float4*)pb0;
        float4 b1 = *(const float4*)pb1;
        float av0[4] = {a0.x, a0.y, a0.z, a0.w};
        float av1[4] = {a1.x, a1.y, a1.z, a1.w};
        float bv0[4] = {b0.x, b0.y, b0.z, b0.w};
        float bv1[4] = {b1.x, b1.y, b1.z, b1.w};
#pragma unroll
        for (int e = 0; e < 4; e++) {
            As[0][lk + e][lr]      = av0[e];
            As[0][lk + e][lr + 64] = av1[e];
            Bs[0][lk + e][lr]      = bv0[e];
            Bs[0][lk + e][lr + 64] = bv1[e];
        }
    }
    __syncthreads();

    for (int kt = 0; kt < ktiles; ++kt) {
        const int cur = kt & 1;
        const int nxt = cur ^ 1;

        float4 na0, na1, nb0, nb1;
        const bool more = (kt + 1 < ktiles);
        if (more) {
            const int off = (kt + 1) * BK;
            na0 = *(const float4*)(pa0 + off);
            na1 = *(const float4*)(pa1 + off);
            nb0 = *(const float4*)(pb0 + off);
            nb1 = *(const float4*)(pb1 + off);
        }

#pragma unroll
        for (int k = 0; k < BK; k++) {
            float af[TM], bf[TN];
#pragma unroll
            for (int i = 0; i < TM; i++) af[i] = As[cur][k][row0 + i];
#pragma unroll
            for (int j = 0; j < TN; j++) bf[j] = Bs[cur][k][col0 + j];
#pragma unroll
            for (int i = 0; i < TM; i++)
#pragma unroll
                for (int j = 0; j < TN; j++)
                    acc[i][j] = fmaf(af[i], bf[j], acc[i][j]);
        }

        if (more) {
            float av0[4] = {na0.x, na0.y, na0.z, na0.w};
            float av1[4] = {na1.x, na1.y, na1.z, na1.w};
            float bv0[4] = {nb0.x, nb0.y, nb0.z, nb0.w};
            float bv1[4] = {nb1.x, nb1.y, nb1.z, nb1.w};
#pragma unroll
            for (int e = 0; e < 4; e++) {
                As[nxt][lk + e][lr]      = av0[e];
                As[nxt][lk + e][lr + 64] = av1[e];
                Bs[nxt][lk + e][lr]      = bv0[e];
                Bs[nxt][lk + e][lr + 64] = bv1[e];
            }
        }
        __syncthreads();
    }

#pragma unroll
    for (int i = 0; i < TM; i++) {
        const size_t rbase = (size_t)(bm + row0 + i) * H + bn + col0;
#pragma unroll
        for (int j = 0; j < TN; j++) {
            out[rbase + j] = acc[i][j];
        }
    }
}

// ---------------------------------------------------------------------------
// Launch. Inputs (metadata order): x [B,S,H], w_gate [I,H], w_up [I,H],
// w_down [H,I], avg_gate [I]. Output: fp32 [B,S,H].
// ---------------------------------------------------------------------------
extern "C" void kernel_launch(void* const* d_in, const int* in_sizes, int n_in,
                              void* d_out, int out_size)
{
    const float* x   = (const float*)d_in[0];
    const float* wg  = (const float*)d_in[1];
    const float* wu  = (const float*)d_in[2];
    const float* wd  = (const float*)d_in[3];
    const float* avg = (const float*)d_in[4];
    float* out = (float*)d_out;

    const int I = in_sizes[4];            // 14336
    const int H = in_sizes[3] / I;        // 4096
    const int M = in_sizes[0] / H;        // 8192

    dim3 g1(I / 64, M / 128);             // 224 x 64
    fused_upgate_kernel<<<g1, 256>>>(x, wg, wu, avg, M, H, I);

    dim3 g2(H / 128, M / 128);            // 32 x 64
    down_kernel<<<g2, 256>>>(wd, out, M, H, I);
}

// round 4
// speedup vs baseline: 2.5383x; 2.5383x over previous
#include <cuda_runtime.h>
#include <math.h>
#include <stdint.h>

// ---------------------------------------------------------------------------
// Feature detection: tcgen05 is arch-SPECIFIC (sm_103a / sm_100a). A plain
// compute_103 PTX pass must not see tcgen05 instructions.
// ---------------------------------------------------------------------------
#ifdef __CUDA_ARCH_HAS_FEATURE__
#define TC_FEAT_103 __CUDA_ARCH_HAS_FEATURE__(SM103_ALL)
#define TC_FEAT_100 __CUDA_ARCH_HAS_FEATURE__(SM100_ALL)
#else
#define TC_FEAT_103 0
#define TC_FEAT_100 0
#endif
#if defined(__CUDA_ARCH__) && (TC_FEAT_103 || TC_FEAT_100 || \
    defined(__CUDA_ARCH_FEAT_SM103_ALL) || defined(__CUDA_ARCH_FEAT_SM100_ALL))
#define TC_OK 1
#else
#define TC_OK 0
#endif

// ---------------------------------------------------------------------------
// Scratch: t split into tf32 hi/lo. Fallback path uses g_t_hi as full t.
// Fix-list: elements whose |up*avg| is within FIX_DELTA of the 0.5 threshold.
// ---------------------------------------------------------------------------
static __device__ float g_t_hi[117440512ull]; // 8192*14336 = 470 MB
static __device__ float g_t_lo[117440512ull]; // 470 MB
static constexpr unsigned FIX_CAP = 8388608u; // 8M entries, 32 MB
static __device__ unsigned g_fix_cnt;
static __device__ unsigned g_fix_list[FIX_CAP];

static constexpr int SMEM_BYTES = 1024 + 6 * 16384 * 2; // 197632, both kernels
#define FIX_DELTA 2.0e-3f

// tf32 round + split helpers (tf32 cvt is sm_80+, NOT arch-specific — safe
// outside the TC_OK guard; the correction kernel needs it on all passes).
__device__ __forceinline__ float tf32_rn(float a) {
    uint32_t r;
    asm("cvt.rna.tf32.f32 %0, %1;" : "=r"(r) : "f"(a));
    return __uint_as_float(r);
}

#if TC_OK
// ===========================================================================
// tcgen05 helpers (compiled ONLY for arch-specific passes)
// ===========================================================================
#define SWZ(o) ((o) ^ (((o) >> 3) & 0x70))

__device__ __forceinline__ uint32_t smem_u32(const void* p) {
    uint32_t a;
    asm("{ .reg .u64 t; cvta.to.shared.u64 t, %1; cvt.u32.u64 %0, t; }"
        : "=r"(a) : "l"(p));
    return a;
}

__device__ __forceinline__ uint32_t elect_one() {
    uint32_t p;
    asm volatile("{ .reg .pred p; elect.sync _|p, 0xFFFFFFFF; selp.b32 %0, 1, 0, p; }"
                 : "=r"(p));
    return p;
}

__device__ __forceinline__ void mbar_init(uint32_t addr, uint32_t cnt) {
    asm volatile("mbarrier.init.shared.b64 [%0], %1;" :: "r"(addr), "r"(cnt) : "memory");
}

__device__ __forceinline__ void mbar_wait(uint32_t mbar, int parity) {
    uint32_t done;
    asm volatile("{\n\t.reg .pred p;\n\t"
                 "mbarrier.try_wait.parity.acquire.cta.shared::cta.b64 p, [%1], %2;\n\t"
                 "selp.b32 %0, 1, 0, p;\n\t}"
                 : "=r"(done) : "r"(mbar), "r"((uint32_t)parity) : "memory");
    while (!done) {
        asm volatile("{\n\t.reg .pred p;\n\t"
                     "mbarrier.try_wait.parity.acquire.cta.shared::cta.b64 p, [%1], %2, 0x989680;\n\t"
                     "selp.b32 %0, 1, 0, p;\n\t}"
                     : "=r"(done) : "r"(mbar), "r"((uint32_t)parity) : "memory");
    }
}

__device__ __forceinline__ void tmem_alloc(uint32_t smem_dst, uint32_t ncols) {
    asm volatile("tcgen05.alloc.cta_group::1.sync.aligned.shared::cta.b32 [%0], %1;"
                 :: "r"(smem_dst), "r"(ncols) : "memory");
}
__device__ __forceinline__ void tmem_dealloc(uint32_t tmem, uint32_t ncols) {
    asm volatile("tcgen05.relinquish_alloc_permit.cta_group::1.sync.aligned;");
    asm volatile("tcgen05.dealloc.cta_group::1.sync.aligned.b32 %0, %1;" :: "r"(tmem), "r"(ncols));
}

__device__ __forceinline__ void mma_commit(uint32_t mbar) {
    asm volatile("tcgen05.commit.cta_group::1.mbarrier::arrive::one.shared::cluster.b64 [%0];"
                 :: "r"(mbar) : "memory");
}

// SS-mode tf32 MMA: D[128,128] += A[128,8] * B[128,8]^T
__device__ __forceinline__ void mma_tf32_ss(uint32_t d, uint64_t a_desc, uint64_t b_desc,
                                            uint32_t idesc, uint32_t en) {
    asm volatile("{\n\t.reg .pred p;\n\tsetp.ne.u32 p, %4, 0;\n\t"
                 "tcgen05.mma.cta_group::1.kind::tf32 [%0], %1, %2, %3, p;\n\t}"
                 :: "r"(d), "l"(a_desc), "l"(b_desc), "r"(idesc), "r"(en) : "memory");
}

// SW128 K-major descriptor: LBO=1, SBO=64, layout=2, version=1.
__device__ __forceinline__ uint64_t sdesc(uint32_t addr) {
    constexpr uint64_t BASE = (2ull << 61) | (1ull << 46) | (64ull << 32) | (1ull << 16);
    return BASE | ((uint64_t)(addr >> 4) & 0x3FFFull);
}

__device__ __forceinline__ void ldtm_x32(uint32_t* r, uint32_t addr) {
    asm volatile(
        "tcgen05.ld.sync.aligned.32x32b.x32.b32 "
        "{%0, %1, %2, %3, %4, %5, %6, %7, "
        " %8, %9, %10, %11, %12, %13, %14, %15, "
        " %16, %17, %18, %19, %20, %21, %22, %23, "
        " %24, %25, %26, %27, %28, %29, %30, %31}, [%32];"
        : "=r"(r[0]),  "=r"(r[1]),  "=r"(r[2]),  "=r"(r[3]),
          "=r"(r[4]),  "=r"(r[5]),  "=r"(r[6]),  "=r"(r[7]),
          "=r"(r[8]),  "=r"(r[9]),  "=r"(r[10]), "=r"(r[11]),
          "=r"(r[12]), "=r"(r[13]), "=r"(r[14]), "=r"(r[15]),
          "=r"(r[16]), "=r"(r[17]), "=r"(r[18]), "=r"(r[19]),
          "=r"(r[20]), "=r"(r[21]), "=r"(r[22]), "=r"(r[23]),
          "=r"(r[24]), "=r"(r[25]), "=r"(r[26]), "=r"(r[27]),
          "=r"(r[28]), "=r"(r[29]), "=r"(r[30]), "=r"(r[31])
        : "r"(addr));
}

#define TCGEN05_WAIT_LD()      asm volatile("tcgen05.wait::ld.sync.aligned;" ::: "memory")
#define FENCE_ASYNC_SHARED()   asm volatile("fence.proxy.async.shared::cta;" ::: "memory")
#define TCGEN05_FENCE_AFTER()  asm volatile("tcgen05.fence::after_thread_sync;" ::: "memory")
#define TCGEN05_FENCE_BEFORE() asm volatile("tcgen05.fence::before_thread_sync;" ::: "memory")

// idesc: c=F32, a=b=TF32, K-major, N=128, M=128
static constexpr uint32_t IDESC_TF32 =
    (1u << 4) | (2u << 7) | (2u << 10) | ((128u / 8u) << 17) | ((128u / 16u) << 24);

__device__ __forceinline__ void split_store4(char* smem_hi, char* smem_lo, float4 v) {
    float4 h, l;
    h.x = tf32_rn(v.x); l.x = tf32_rn(v.x - h.x);
    h.y = tf32_rn(v.y); l.y = tf32_rn(v.y - h.y);
    h.z = tf32_rn(v.z); l.z = tf32_rn(v.z - h.z);
    h.w = tf32_rn(v.w); l.w = tf32_rn(v.w - h.w);
    *(float4*)smem_hi = h;
    *(float4*)smem_lo = l;
}
#endif // TC_OK

// ===========================================================================
// Reset kernel: zero the fix-list counter (graph-capturable, deterministic).
// ===========================================================================
__global__ void reset_fix_cnt() {
    if (threadIdx.x == 0 && blockIdx.x == 0) g_fix_cnt = 0;
}

// ===========================================================================
// Kernel 1: fused up+gate (TF32x3 tcgen05; FFMA fallback).
// Epilogue: mask+silu, write split t, FLAG near-threshold elements.
// ===========================================================================
__global__ __launch_bounds__(256)
void upgate_mma(const float* __restrict__ x, const float* __restrict__ wg,
                const float* __restrict__ wu, const float* __restrict__ avg,
                int M, int H, int I)
{
#if TC_OK
    extern __shared__ char smem[];
    const uint32_t sb = smem_u32(smem);
    const uint32_t mbar0 = sb + 16, mbar1 = sb + 24;
    float* avg_s = (float*)(smem + 64);
    constexpr uint32_t STAGE0 = 1024;
    constexpr uint32_t STAGE_STRIDE = 6 * 16384;

    const int tid = threadIdx.x;
    const int wid = tid >> 5;
    const int lane = tid & 31;
    const int bn = blockIdx.x * 128;
    const int bm = blockIdx.y * 128;

    if (wid == 0) tmem_alloc(sb, 256);
    if (tid == 0) { mbar_init(mbar0, 1); mbar_init(mbar1, 1); }
    if (tid < 128) avg_s[tid] = avg[bn + tid];
    __syncthreads();
    const uint32_t tmem = *(volatile uint32_t*)smem;
    const uint32_t d_up = tmem, d_gate = tmem + 128;

    const int r0 = tid >> 3;            // 0..31
    const int c4 = (tid & 7) * 4;       // float col within 32-wide chunk
    const int nchunks = H / 32;
    int ph0 = 0, ph1 = 0;

    for (int kt = 0; kt < nchunks; ++kt) {
        const int s = kt & 1;
        char* stg = smem + STAGE0 + (uint32_t)s * STAGE_STRIDE;

        if (kt >= 2) {
            if (s == 0) { mbar_wait(mbar0, ph0); ph0 ^= 1; }
            else        { mbar_wait(mbar1, ph1); ph1 ^= 1; }
        }

        const size_t gk = (size_t)kt * 32 + c4;
        float4 vx[4], vu[4], vg[4];
#pragma unroll
        for (int it = 0; it < 4; ++it) {
            const int row = r0 + it * 32;
            vx[it] = *(const float4*)(x  + (size_t)(bm + row) * H + gk);
            vu[it] = *(const float4*)(wu + (size_t)(bn + row) * H + gk);
            vg[it] = *(const float4*)(wg + (size_t)(bn + row) * H + gk);
        }
#pragma unroll
        for (int it = 0; it < 4; ++it) {
            const int row = r0 + it * 32;
            const uint32_t so = SWZ((uint32_t)(row * 128 + c4 * 4));
            split_store4(stg + 0 * 16384 + so, stg + 1 * 16384 + so, vx[it]);
            split_store4(stg + 2 * 16384 + so, stg + 3 * 16384 + so, vu[it]);
            split_store4(stg + 4 * 16384 + so, stg + 5 * 16384 + so, vg[it]);
        }
        __syncthreads();

        if (wid == 0 && elect_one()) {
            FENCE_ASYNC_SHARED();
            const uint32_t sa = sb + STAGE0 + (uint32_t)s * STAGE_STRIDE;
            const uint64_t aH = sdesc(sa),          aL = sdesc(sa + 16384);
            const uint64_t uH = sdesc(sa + 32768),  uL = sdesc(sa + 49152);
            const uint64_t gH = sdesc(sa + 65536),  gL = sdesc(sa + 81920);
#pragma unroll
            for (int st = 0; st < 4; ++st) {
                const uint32_t en = (kt > 0 || st > 0) ? 1u : 0u;
                const uint64_t o = (uint64_t)(st * 2);
                mma_tf32_ss(d_up,   aH + o, uH + o, IDESC_TF32, en);
                mma_tf32_ss(d_up,   aH + o, uL + o, IDESC_TF32, 1u);
                mma_tf32_ss(d_up,   aL + o, uH + o, IDESC_TF32, 1u);
                mma_tf32_ss(d_gate, aH + o, gH + o, IDESC_TF32, en);
                mma_tf32_ss(d_gate, aH + o, gL + o, IDESC_TF32, 1u);
                mma_tf32_ss(d_gate, aL + o, gH + o, IDESC_TF32, 1u);
            }
            mma_commit(s == 0 ? mbar0 : mbar1);
        }
    }

    mbar_wait(mbar0, ph0);
    mbar_wait(mbar1, ph1);
    TCGEN05_FENCE_AFTER();

    {
        const int sub = wid & 3;
        const int token = bm + sub * 32 + lane;
        const int cc0 = (wid >> 2) * 2;
#pragma unroll
        for (int cc = cc0; cc < cc0 + 2; ++cc) {
            uint32_t ru[32], rg[32];
            ldtm_x32(ru, d_up + cc * 32);
            ldtm_x32(rg, d_gate + cc * 32);
            TCGEN05_WAIT_LD();
            const size_t base = (size_t)token * I + bn + cc * 32;
#pragma unroll
            for (int q = 0; q < 8; ++q) {
                float4 h4, l4;
                float* hp = (float*)&h4;
                float* lp = (float*)&l4;
#pragma unroll
                for (int e = 0; e < 4; ++e) {
                    const int j = q * 4 + e;
                    const float up = __uint_as_float(ru[j]);
                    const float g  = __uint_as_float(rg[j]);
                    const float a  = avg_s[cc * 32 + j];
                    const float m  = fabsf(up * a);
                    float v = 0.0f;
                    if (m >= 0.5f) v = (g / (1.0f + expf(-g))) * up;
                    // Flag near-threshold elements for exact recompute.
                    if (fabsf(m - 0.5f) < FIX_DELTA) {
                        const unsigned idx = atomicAdd(&g_fix_cnt, 1u);
                        if (idx < FIX_CAP)
                            g_fix_list[idx] = ((unsigned)token << 14) | (unsigned)(bn + cc * 32 + j);
                    }
                    const float h = tf32_rn(v);
                    hp[e] = h;
                    lp[e] = tf32_rn(v - h);
                }
                *(float4*)(g_t_hi + base + q * 4) = h4;
                *(float4*)(g_t_lo + base + q * 4) = l4;
            }
        }
    }
    TCGEN05_FENCE_BEFORE();
    __syncthreads();
    if (wid == 0) tmem_dealloc(tmem, 256);

#else // ---------------- fallback: round-1 FFMA pipeline -------------------
    extern __shared__ char smem_raw[];
    constexpr int BK = 16, TM = 8, TN = 4, AST = 132, BST = 68;
    float* AsS = (float*)smem_raw;
    float* BuS = AsS + 2 * BK * AST;
    float* BgS = BuS + 2 * BK * BST;
#define A_AT(s,k,r) AsS[((s) * BK + (k)) * AST + (r)]
#define U_AT(s,k,r) BuS[((s) * BK + (k)) * BST + (r)]
#define G_AT(s,k,r) BgS[((s) * BK + (k)) * BST + (r)]

    const int tid = threadIdx.x;
    const int tx = tid & 15, ty = tid >> 4;
    const int row0 = ty * TM, col0 = tx * TN;
    const int lr = tid >> 2, lk = (tid & 3) * 4;
    const int bm = blockIdx.y * 128;
    const int bnBase = blockIdx.x * 128;
    const int ktiles = H / BK;

    for (int half = 0; half < 2; ++half) {
        const int bn = bnBase + half * 64;
        const float* pa0 = x  + (size_t)(bm + lr)      * H + lk;
        const float* pa1 = x  + (size_t)(bm + lr + 64) * H + lk;
        const float* pbu = wu + (size_t)(bn + lr)      * H + lk;
        const float* pbg = wg + (size_t)(bn + lr)      * H + lk;

        float accU[TM][TN] = {};
        float accG[TM][TN] = {};

        {
            float4 a0 = *(const float4*)pa0;
            float4 a1 = *(const float4*)pa1;
            float4 b0 = *(const float4*)pbu;
            float4 b1 = *(const float4*)pbg;
            float av0[4] = {a0.x, a0.y, a0.z, a0.w};
            float av1[4] = {a1.x, a1.y, a1.z, a1.w};
            float bv0[4] = {b0.x, b0.y, b0.z, b0.w};
            float bv1[4] = {b1.x, b1.y, b1.z, b1.w};
#pragma unroll
            for (int e = 0; e < 4; e++) {
                A_AT(0, lk + e, lr)      = av0[e];
                A_AT(0, lk + e, lr + 64) = av1[e];
                U_AT(0, lk + e, lr)      = bv0[e];
                G_AT(0, lk + e, lr)      = bv1[e];
            }
        }
        __syncthreads();

        for (int kt = 0; kt < ktiles; ++kt) {
            const int cur = kt & 1, nxt = cur ^ 1;
            float4 na0, na1, nbu, nbg;
            const bool more = (kt + 1 < ktiles);
            if (more) {
                const int off = (kt + 1) * BK;
                na0 = *(const float4*)(pa0 + off);
                na1 = *(const float4*)(pa1 + off);
                nbu = *(const float4*)(pbu + off);
                nbg = *(const float4*)(pbg + off);
            }
#pragma unroll
            for (int k = 0; k < BK; k++) {
                float af[TM], uf[TN], gf[TN];
#pragma unroll
                for (int i = 0; i < TM; i++) af[i] = A_AT(cur, k, row0 + i);
#pragma unroll
                for (int j = 0; j < TN; j++) {
                    uf[j] = U_AT(cur, k, col0 + j);
                    gf[j] = G_AT(cur, k, col0 + j);
                }
#pragma unroll
                for (int i = 0; i < TM; i++)
#pragma unroll
                    for (int j = 0; j < TN; j++) {
                        accU[i][j] = fmaf(af[i], uf[j], accU[i][j]);
                        accG[i][j] = fmaf(af[i], gf[j], accG[i][j]);
                    }
            }
            if (more) {
                float av0[4] = {na0.x, na0.y, na0.z, na0.w};
                float av1[4] = {na1.x, na1.y, na1.z, na1.w};
                float bv0[4] = {nbu.x, nbu.y, nbu.z, nbu.w};
                float bv1[4] = {nbg.x, nbg.y, nbg.z, nbg.w};
#pragma unroll
                for (int e = 0; e < 4; e++) {
                    A_AT(nxt, lk + e, lr)      = av0[e];
                    A_AT(nxt, lk + e, lr + 64) = av1[e];
                    U_AT(nxt, lk + e, lr)      = bv0[e];
                    G_AT(nxt, lk + e, lr)      = bv1[e];
                }
            }
            __syncthreads();
        }

#pragma unroll
        for (int j = 0; j < TN; j++) {
            const int col = bn + col0 + j;
            const float a = avg[col];
#pragma unroll
            for (int i = 0; i < TM; i++) {
                const float up = accU[i][j];
                const float g  = accG[i][j];
                float v = 0.0f;
                if (fabsf(up * a) >= 0.5f) v = (g / (1.0f + expf(-g))) * up;
                g_t_hi[(size_t)(bm + row0 + i) * I + col] = v;
            }
        }
        __syncthreads();
    }
#undef A_AT
#undef U_AT
#undef G_AT
#endif
}

// ===========================================================================
// Correction kernel: exact FFMA recompute of flagged (token, neuron) pairs.
// Warp per element; grid-stride over the device-side list.
// ===========================================================================
__global__ __launch_bounds__(256)
void fix_mask_kernel(const float* __restrict__ x, const float* __restrict__ wg,
                     const float* __restrict__ wu, const float* __restrict__ avg,
                     int H, int I)
{
    const unsigned raw = g_fix_cnt;
    const unsigned n = raw < FIX_CAP ? raw : FIX_CAP;
    const unsigned warp_g = (blockIdx.x * blockDim.x + threadIdx.x) >> 5;
    const unsigned nwarps = (gridDim.x * blockDim.x) >> 5;
    const int lane = threadIdx.x & 31;

    for (unsigned i = warp_g; i < n; i += nwarps) {
        const unsigned code = g_fix_list[i];
        const int token  = (int)(code >> 14);
        const int neuron = (int)(code & 16383u);
        const float* xr = x  + (size_t)token  * H;
        const float* ur = wu + (size_t)neuron * H;
        const float* gr = wg + (size_t)neuron * H;

        float du = 0.0f, dg = 0.0f;
        for (int k = lane * 4; k < H; k += 128) {
            const float4 xv = *(const float4*)(xr + k);
            const float4 uv = *(const float4*)(ur + k);
            const float4 gv = *(const float4*)(gr + k);
            du = fmaf(xv.x, uv.x, fmaf(xv.y, uv.y, fmaf(xv.z, uv.z, fmaf(xv.w, uv.w, du))));
            dg = fmaf(xv.x, gv.x, fmaf(xv.y, gv.y, fmaf(xv.z, gv.z, fmaf(xv.w, gv.w, dg))));
        }
#pragma unroll
        for (int o = 16; o; o >>= 1) {
            du += __shfl_xor_sync(0xFFFFFFFFu, du, o);
            dg += __shfl_xor_sync(0xFFFFFFFFu, dg, o);
        }
        if (lane == 0) {
            float v = 0.0f;
            if (fabsf(du * avg[neuron]) >= 0.5f)
                v = (dg / (1.0f + expf(-dg))) * du;
            const float h = tf32_rn(v);
            const size_t o = (size_t)token * I + neuron;
            g_t_hi[o] = h;
            g_t_lo[o] = tf32_rn(v - h);
        }
    }
}

// ===========================================================================
// Kernel 2: down projection. out = t @ w_down^T (TF32x3; FFMA fallback).
// ===========================================================================
__global__ __launch_bounds__(256)
void down_mma(const float* __restrict__ wd, float* __restrict__ out,
              int M, int H, int I)
{
#if TC_OK
    extern __shared__ char smem[];
    const uint32_t sb = smem_u32(smem);
    constexpr uint32_t STAGE0 = 1024;
    constexpr uint32_t STAGE_STRIDE = 4 * 16384;

    const int tid = threadIdx.x;
    const int wid = tid >> 5;
    const int lane = tid & 31;
    const int bn = blockIdx.x * 128;
    const int bm = blockIdx.y * 128;

    if (wid == 0) tmem_alloc(sb, 128);
    if (tid == 0) { mbar_init(sb + 16, 1); mbar_init(sb + 24, 1); mbar_init(sb + 32, 1); }
    __syncthreads();
    const uint32_t tmem = *(volatile uint32_t*)smem;

    const int r0 = tid >> 3;
    const int c4 = (tid & 7) * 4;
    const int nchunks = I / 32;
    int ph[3] = {0, 0, 0};

    for (int kt = 0; kt < nchunks; ++kt) {
        const int s = kt % 3;
        char* stg = smem + STAGE0 + (uint32_t)s * STAGE_STRIDE;
        const uint32_t mb = sb + 16 + 8 * s;

        if (kt >= 3) { mbar_wait(mb, ph[s]); ph[s] ^= 1; }

        const size_t gk = (size_t)kt * 32 + c4;
        float4 ah[4], al[4], bw[4];
#pragma unroll
        for (int it = 0; it < 4; ++it) {
            const int row = r0 + it * 32;
            ah[it] = *(const float4*)(g_t_hi + (size_t)(bm + row) * I + gk);
            al[it] = *(const float4*)(g_t_lo + (size_t)(bm + row) * I + gk);
            bw[it] = *(const float4*)(wd     + (size_t)(bn + row) * I + gk);
        }
#pragma unroll
        for (int it = 0; it < 4; ++it) {
            const int row = r0 + it * 32;
            const uint32_t so = SWZ((uint32_t)(row * 128 + c4 * 4));
            *(float4*)(stg + 0 * 16384 + so) = ah[it];
            *(float4*)(stg + 1 * 16384 + so) = al[it];
            split_store4(stg + 2 * 16384 + so, stg + 3 * 16384 + so, bw[it]);
        }
        __syncthreads();

        if (wid == 0 && elect_one()) {
            FENCE_ASYNC_SHARED();
            const uint32_t sa = sb + STAGE0 + (uint32_t)s * STAGE_STRIDE;
            const uint64_t aH = sdesc(sa),         aL = sdesc(sa + 16384);
            const uint64_t bH = sdesc(sa + 32768), bL = sdesc(sa + 49152);
#pragma unroll
            for (int st = 0; st < 4; ++st) {
                const uint32_t en = (kt > 0 || st > 0) ? 1u : 0u;
                const uint64_t o = (uint64_t)(st * 2);
                mma_tf32_ss(tmem, aH + o, bH + o, IDESC_TF32, en);
                mma_tf32_ss(tmem, aH + o, bL + o, IDESC_TF32, 1u);
                mma_tf32_ss(tmem, aL + o, bH + o, IDESC_TF32, 1u);
            }
            mma_commit(mb);
        }
    }

    mbar_wait(sb + 16, ph[0]);
    mbar_wait(sb + 24, ph[1]);
    mbar_wait(sb + 32, ph[2]);
    TCGEN05_FENCE_AFTER();

    {
        const int sub = wid & 3;
        const int token = bm + sub * 32 + lane;
        const int cc0 = (wid >> 2) * 2;
#pragma unroll
        for (int cc = cc0; cc < cc0 + 2; ++cc) {
            uint32_t r[32];
            ldtm_x32(r, tmem + cc * 32);
            TCGEN05_WAIT_LD();
            const size_t base = (size_t)token * H + bn + cc * 32;
#pragma unroll
            for (int q = 0; q < 8; ++q) {
                float4 v4;
                ((float*)&v4)[0] = __uint_as_float(r[q * 4 + 0]);
                ((float*)&v4)[1] = __uint_as_float(r[q * 4 + 1]);
                ((float*)&v4)[2] = __uint_as_float(r[q * 4 + 2]);
                ((float*)&v4)[3] = __uint_as_float(r[q * 4 + 3]);
                *(float4*)(out + base + q * 4) = v4;
            }
        }
    }
    TCGEN05_FENCE_BEFORE();
    __syncthreads();
    if (wid == 0) tmem_dealloc(tmem, 128);

#else // ---------------- fallback: round-1 FFMA down -----------------------
    extern __shared__ char smem_raw[];
    constexpr int BK = 16, TM = 8, TN = 8, AST = 132;
    float* AsS = (float*)smem_raw;
    float* BsS = AsS + 2 * BK * AST;
#define A_AT(s,k,r) AsS[((s) * BK + (k)) * AST + (r)]
#define B_AT(s,k,r) BsS[((s) * BK + (k)) * AST + (r)]

    const int tid = threadIdx.x;
    const int tx = tid & 15, ty = tid >> 4;
    const int row0 = ty * TM, col0 = tx * TN;
    const int lr = tid >> 2, lk = (tid & 3) * 4;
    const int bn = blockIdx.x * 128;
    const int bm = blockIdx.y * 128;

    const float* pa0 = g_t_hi + (size_t)(bm + lr)      * I + lk;
    const float* pa1 = g_t_hi + (size_t)(bm + lr + 64) * I + lk;
    const float* pb0 = wd     + (size_t)(bn + lr)      * I + lk;
    const float* pb1 = wd     + (size_t)(bn + lr + 64) * I + lk;

    float acc[TM][TN] = {};
    const int ktiles = I / BK;

    {
        float4 a0 = *(const float4*)pa0;
        float4 a1 = *(const float4*)pa1;
        float4 b0 = *(const float4*)pb0;
        float4 b1 = *(const float4*)pb1;
        float av0[4] = {a0.x, a0.y, a0.z, a0.w};
        float av1[4] = {a1.x, a1.y, a1.z, a1.w};
        float bv0[4] = {b0.x, b0.y, b0.z, b0.w};
        float bv1[4] = {b1.x, b1.y, b1.z, b1.w};
#pragma unroll
        for (int e = 0; e < 4; e++) {
            A_AT(0, lk + e, lr)      = av0[e];
            A_AT(0, lk + e, lr + 64) = av1[e];
            B_AT(0, lk + e, lr)      = bv0[e];
            B_AT(0, lk + e, lr + 64) = bv1[e];
        }
    }
    __syncthreads();

    for (int kt = 0; kt < ktiles; ++kt) {
        const int cur = kt & 1, nxt = cur ^ 1;
        float4 na0, na1, nb0, nb1;
        const bool more = (kt + 1 < ktiles);
        if (more) {
            const int off = (kt + 1) * BK;
            na0 = *(const float4*)(pa0 + off);
            na1 = *(const float4*)(pa1 + off);
            nb0 = *(const float4*)(pb0 + off);
            nb1 = *(const float4*)(pb1 + off);
        }
#pragma unroll
        for (int k = 0; k < BK; k++) {
            float af[TM], bf[TN];
#pragma unroll
            for (int i = 0; i < TM; i++) af[i] = A_AT(cur, k, row0 + i);
#pragma unroll
            for (int j = 0; j < TN; j++) bf[j] = B_AT(cur, k, col0 + j);
#pragma unroll
            for (int i = 0; i < TM; i++)
#pragma unroll
                for (int j = 0; j < TN; j++)
                    acc[i][j] = fmaf(af[i], bf[j], acc[i][j]);
        }
        if (more) {
            float av0[4] = {na0.x, na0.y, na0.z, na0.w};
            float av1[4] = {na1.x, na1.y, na1.z, na1.w};
            float bv0[4] = {nb0.x, nb0.y, nb0.z, nb0.w};
            float bv1[4] = {nb1.x, nb1.y, nb1.z, nb1.w};
#pragma unroll
            for (int e = 0; e < 4; e++) {
                A_AT(nxt, lk + e, lr)      = av0[e];
                A_AT(nxt, lk + e, lr + 64) = av1[e];
                B_AT(nxt, lk + e, lr)      = bv0[e];
                B_AT(nxt, lk + e, lr + 64) = bv1[e];
            }
        }
        __syncthreads();
    }

#pragma unroll
    for (int i = 0; i < TM; i++) {
        const size_t rbase = (size_t)(bm + row0 + i) * H + bn + col0;
#pragma unroll
        for (int j = 0; j < TN; j++) out[rbase + j] = acc[i][j];
    }
#undef A_AT
#undef B_AT
#endif
}

// ---------------------------------------------------------------------------
// Launch: reset -> upgate (+flag) -> fix -> down
// ---------------------------------------------------------------------------
extern "C" void kernel_launch(void* const* d_in, const int* in_sizes, int n_in,
                              void* d_out, int out_size)
{
    const float* x   = (const float*)d_in[0];
    const float* wg  = (const float*)d_in[1];
    const float* wu  = (const float*)d_in[2];
    const float* wd  = (const float*)d_in[3];
    const float* avg = (const float*)d_in[4];
    float* out = (float*)d_out;

    const int I = in_sizes[4];            // 14336
    const int H = in_sizes[3] / I;        // 4096
    const int M = in_sizes[0] / H;        // 8192

    cudaFuncSetAttribute(upgate_mma, cudaFuncAttributeMaxDynamicSharedMemorySize, SMEM_BYTES);
    cudaFuncSetAttribute(down_mma,   cudaFuncAttributeMaxDynamicSharedMemorySize, SMEM_BYTES);

    reset_fix_cnt<<<1, 32>>>();

    dim3 g1(I / 128, M / 128);            // 112 x 64
    upgate_mma<<<g1, 256, SMEM_BYTES>>>(x, wg, wu, avg, M, H, I);

    fix_mask_kernel<<<1024, 256>>>(x, wg, wu, avg, H, I);

    dim3 g2(H / 128, M / 128);            // 32 x 64
    down_mma<<<g2, 256, SMEM_BYTES>>>(wd, out, M, H, I);
}

// round 5
// speedup vs baseline: 5.1527x; 2.0300x over previous
#include <cuda_runtime.h>
#include <math.h>
#include <stdint.h>

// ---------------------------------------------------------------------------
// Feature detection: tcgen05 is arch-SPECIFIC (sm_103a / sm_100a).
// ---------------------------------------------------------------------------
#ifdef __CUDA_ARCH_HAS_FEATURE__
#define TC_FEAT_103 __CUDA_ARCH_HAS_FEATURE__(SM103_ALL)
#define TC_FEAT_100 __CUDA_ARCH_HAS_FEATURE__(SM100_ALL)
#else
#define TC_FEAT_103 0
#define TC_FEAT_100 0
#endif
#if defined(__CUDA_ARCH__) && (TC_FEAT_103 || TC_FEAT_100 || \
    defined(__CUDA_ARCH_FEAT_SM103_ALL) || defined(__CUDA_ARCH_FEAT_SM100_ALL))
#define TC_OK 1
#else
#define TC_OK 0
#endif

// ---------------------------------------------------------------------------
// Global scratch (static; no allocations allowed).
//   g_t_r  : t = silu(gate*mask)*(up*mask), tf32-rounded   [M, I]
//   g_*_r  : tf32-rounded copies of inputs (MMA operands)
// ---------------------------------------------------------------------------
static __device__ float g_t_r [117440512ull]; // 8192*14336
static __device__ float g_x_r [33554432ull];  // 8192*4096
static __device__ float g_wu_r[58720256ull];  // 14336*4096
static __device__ float g_wg_r[58720256ull];
static __device__ float g_wd_r[58720256ull];  // 4096*14336
static constexpr unsigned FIX_CAP = 8388608u;
static __device__ unsigned g_fix_cnt;
static __device__ unsigned g_fix_list[FIX_CAP];

#define FIX_DELTA 2.0e-3f
static constexpr int SMEM_BYTES = 1024 + 4 * 49152; // 197632 (both GEMMs)

// tf32 round (sm_80+, safe on every compile pass)
__device__ __forceinline__ float tf32_rn(float a) {
    uint32_t r;
    asm("cvt.rna.tf32.f32 %0, %1;" : "=r"(r) : "f"(a));
    return __uint_as_float(r);
}

#if TC_OK
// ===========================================================================
// sm_103a helpers
// ===========================================================================
#define SWZ(o) ((o) ^ (((o) >> 3) & 0x70))

__device__ __forceinline__ uint32_t smem_u32(const void* p) {
    uint32_t a;
    asm("{ .reg .u64 t; cvta.to.shared.u64 t, %1; cvt.u32.u64 %0, t; }"
        : "=r"(a) : "l"(p));
    return a;
}
__device__ __forceinline__ uint32_t elect_one() {
    uint32_t p;
    asm volatile("{ .reg .pred p; elect.sync _|p, 0xFFFFFFFF; selp.b32 %0, 1, 0, p; }"
                 : "=r"(p));
    return p;
}
__device__ __forceinline__ void mbar_init(uint32_t addr, uint32_t cnt) {
    asm volatile("mbarrier.init.shared.b64 [%0], %1;" :: "r"(addr), "r"(cnt) : "memory");
}
__device__ __forceinline__ void mbar_wait(uint32_t mbar, int parity) {
    uint32_t done;
    asm volatile("{\n\t.reg .pred p;\n\t"
                 "mbarrier.try_wait.parity.acquire.cta.shared::cta.b64 p, [%1], %2;\n\t"
                 "selp.b32 %0, 1, 0, p;\n\t}"
                 : "=r"(done) : "r"(mbar), "r"((uint32_t)parity) : "memory");
    while (!done) {
        asm volatile("{\n\t.reg .pred p;\n\t"
                     "mbarrier.try_wait.parity.acquire.cta.shared::cta.b64 p, [%1], %2, 0x989680;\n\t"
                     "selp.b32 %0, 1, 0, p;\n\t}"
                     : "=r"(done) : "r"(mbar), "r"((uint32_t)parity) : "memory");
    }
}
__device__ __forceinline__ void tmem_alloc(uint32_t smem_dst, uint32_t ncols) {
    asm volatile("tcgen05.alloc.cta_group::1.sync.aligned.shared::cta.b32 [%0], %1;"
                 :: "r"(smem_dst), "r"(ncols) : "memory");
}
__device__ __forceinline__ void tmem_dealloc(uint32_t tmem, uint32_t ncols) {
    asm volatile("tcgen05.relinquish_alloc_permit.cta_group::1.sync.aligned;");
    asm volatile("tcgen05.dealloc.cta_group::1.sync.aligned.b32 %0, %1;" :: "r"(tmem), "r"(ncols));
}
__device__ __forceinline__ void mma_commit(uint32_t mbar) {
    asm volatile("tcgen05.commit.cta_group::1.mbarrier::arrive::one.shared::cluster.b64 [%0];"
                 :: "r"(mbar) : "memory");
}
__device__ __forceinline__ void mma_tf32_ss(uint32_t d, uint64_t a_desc, uint64_t b_desc,
                                            uint32_t idesc, uint32_t en) {
    asm volatile("{\n\t.reg .pred p;\n\tsetp.ne.u32 p, %4, 0;\n\t"
                 "tcgen05.mma.cta_group::1.kind::tf32 [%0], %1, %2, %3, p;\n\t}"
                 :: "r"(d), "l"(a_desc), "l"(b_desc), "r"(idesc), "r"(en) : "memory");
}
// SW128 K-major descriptor: LBO=1, SBO=64, layout=2, version=1.
__device__ __forceinline__ uint64_t sdesc(uint32_t addr) {
    constexpr uint64_t BASE = (2ull << 61) | (1ull << 46) | (64ull << 32) | (1ull << 16);
    return BASE | ((uint64_t)(addr >> 4) & 0x3FFFull);
}
__device__ __forceinline__ void ldtm_x32(uint32_t* r, uint32_t addr) {
    asm volatile(
        "tcgen05.ld.sync.aligned.32x32b.x32.b32 "
        "{%0, %1, %2, %3, %4, %5, %6, %7, "
        " %8, %9, %10, %11, %12, %13, %14, %15, "
        " %16, %17, %18, %19, %20, %21, %22, %23, "
        " %24, %25, %26, %27, %28, %29, %30, %31}, [%32];"
        : "=r"(r[0]),  "=r"(r[1]),  "=r"(r[2]),  "=r"(r[3]),
          "=r"(r[4]),  "=r"(r[5]),  "=r"(r[6]),  "=r"(r[7]),
          "=r"(r[8]),  "=r"(r[9]),  "=r"(r[10]), "=r"(r[11]),
          "=r"(r[12]), "=r"(r[13]), "=r"(r[14]), "=r"(r[15]),
          "=r"(r[16]), "=r"(r[17]), "=r"(r[18]), "=r"(r[19]),
          "=r"(r[20]), "=r"(r[21]), "=r"(r[22]), "=r"(r[23]),
          "=r"(r[24]), "=r"(r[25]), "=r"(r[26]), "=r"(r[27]),
          "=r"(r[28]), "=r"(r[29]), "=r"(r[30]), "=r"(r[31])
        : "r"(addr));
}
#define TCGEN05_WAIT_LD()      asm volatile("tcgen05.wait::ld.sync.aligned;" ::: "memory")
#define FENCE_ASYNC_SHARED()   asm volatile("fence.proxy.async.shared::cta;" ::: "memory")
#define TCGEN05_FENCE_AFTER()  asm volatile("tcgen05.fence::after_thread_sync;" ::: "memory")
#define TCGEN05_FENCE_BEFORE() asm volatile("tcgen05.fence::before_thread_sync;" ::: "memory")

__device__ __forceinline__ void cp16(uint32_t dst, const void* src) {
    asm volatile("cp.async.cg.shared.global [%0], [%1], 16;" :: "r"(dst), "l"(src) : "memory");
}
#define CP_COMMIT() asm volatile("cp.async.commit_group;" ::: "memory")
#define CP_WAIT(n)  asm volatile("cp.async.wait_group %0;" :: "n"(n) : "memory")
__device__ __forceinline__ void cp_wait_pend(int pend) {
    if (pend >= 2) { CP_WAIT(2); }
    else if (pend == 1) { CP_WAIT(1); }
    else { CP_WAIT(0); }
}

// idesc: c=F32, a=b=TF32, K-major, N=128, M=128
static constexpr uint32_t IDESC_TF32 =
    (1u << 4) | (2u << 7) | (2u << 10) | ((128u / 8u) << 17) | ((128u / 16u) << 24);
#endif // TC_OK

// ===========================================================================
// Pre-round: dst = tf32_rn(src), elementwise.
// ===========================================================================
__global__ void round_tf32_kernel(float* __restrict__ dst, const float* __restrict__ src,
                                  long long n) {
    long long i = ((long long)blockIdx.x * blockDim.x + threadIdx.x) * 4;
    const long long stride = (long long)gridDim.x * blockDim.x * 4;
    for (; i < n; i += stride) {
        float4 v = *(const float4*)(src + i);
        v.x = tf32_rn(v.x); v.y = tf32_rn(v.y);
        v.z = tf32_rn(v.z); v.w = tf32_rn(v.w);
        *(float4*)(dst + i) = v;
    }
}

__global__ void reset_fix_cnt() {
    if (threadIdx.x == 0 && blockIdx.x == 0) g_fix_cnt = 0;
}

// ===========================================================================
// Kernel 1: fused up+gate. 1-pass TF32, cp.async 4-stage pipeline.
// Tile 128 tokens x 128 neurons, BK=32. Stage = x(16K)+wu(16K)+wg(16K)=48K.
// TMEM: up [0,128), gate [128,256). Epilogue: mask+silu, write t_r, flag.
// ===========================================================================
__global__ __launch_bounds__(256)
void upgate_mma(const float* __restrict__ x, const float* __restrict__ wg,
                const float* __restrict__ wu, const float* __restrict__ avg,
                int M, int H, int I)
{
#if TC_OK
    extern __shared__ char smem[];
    const uint32_t sb = smem_u32(smem);
    float* avg_s = (float*)(smem + 64);
    constexpr uint32_t STAGE0 = 1024, SSZ = 49152;

    const int tid = threadIdx.x;
    const int wid = tid >> 5;
    const int lane = tid & 31;

    // Supertile remap: bands of 8 bm, n-major inside a band.
    const int GX = gridDim.x;
    const int lin = blockIdx.y * GX + blockIdx.x;
    const int band = lin / (8 * GX);
    const int rr = lin - band * 8 * GX;
    const int bn = (rr >> 3) * 128;
    const int bm = (band * 8 + (rr & 7)) * 128;

    if (wid == 0) tmem_alloc(sb, 256);
    if (tid == 0)
#pragma unroll
        for (int s = 0; s < 4; ++s) mbar_init(sb + 16 + 8 * s, 1);
    if (tid < 128) avg_s[tid] = avg[bn + tid];
    __syncthreads();
    const uint32_t tmem = *(volatile uint32_t*)smem;
    const uint32_t d_up = tmem, d_gate = tmem + 128;

    const int lrow = tid >> 1;          // 0..127
    const int lc0  = (tid & 1) * 4;     // seg 0..3 or 4..7 (16B segs of 128B row)
    const int nchunks = H / 32;
    int ph[4] = {0, 0, 0, 0};

    const float* xrow = g_x_r  + (size_t)(bm + lrow) * H;
    const float* urow = g_wu_r + (size_t)(bn + lrow) * H;
    const float* grow = g_wg_r + (size_t)(bn + lrow) * H;

    auto load_stage = [&](int kt, int s) {
        const uint32_t sa = sb + STAGE0 + (uint32_t)s * SSZ;
        const int col0 = kt * 32;
#pragma unroll
        for (int k = 0; k < 4; ++k) {
            const int c = lc0 + k;
            const uint32_t so = SWZ((uint32_t)(lrow * 128 + c * 16));
            cp16(sa +     0 + so, xrow + col0 + c * 4);
            cp16(sa + 16384 + so, urow + col0 + c * 4);
            cp16(sa + 32768 + so, grow + col0 + c * 4);
        }
        CP_COMMIT();
    };

    // Prologue: stages 0..2 in flight.
    load_stage(0, 0); load_stage(1, 1); load_stage(2, 2);

    for (int kt = 0; kt < nchunks; ++kt) {
        cp_wait_pend(nchunks - 1 - kt);
        __syncthreads();

        if (wid == 0 && elect_one()) {
            FENCE_ASYNC_SHARED();
            const uint32_t sa = sb + STAGE0 + (uint32_t)(kt & 3) * SSZ;
            const uint64_t xd = sdesc(sa), ud = sdesc(sa + 16384), gd = sdesc(sa + 32768);
#pragma unroll
            for (int st = 0; st < 4; ++st) {
                const uint32_t en = (kt > 0 || st > 0) ? 1u : 0u;
                const uint64_t o = (uint64_t)(st * 2);
                mma_tf32_ss(d_up,   xd + o, ud + o, IDESC_TF32, en);
                mma_tf32_ss(d_gate, xd + o, gd + o, IDESC_TF32, en);
            }
            mma_commit(sb + 16 + 8 * (kt & 3));
        }

        const int tgt = kt + 3;
        if (tgt < nchunks) {
            const int s = tgt & 3;
            if (tgt >= 4) { mbar_wait(sb + 16 + 8 * s, ph[s]); ph[s] ^= 1; }
            load_stage(tgt, s);
        }
    }
#pragma unroll
    for (int s = 0; s < 4; ++s) mbar_wait(sb + 16 + 8 * s, ph[s]);
    TCGEN05_FENCE_AFTER();

    // Epilogue: mask + silu + flag + write t_r (tf32-rounded).
    {
        const int sub = wid & 3;
        const int token = bm + sub * 32 + lane;
        const int cc0 = (wid >> 2) * 2;
#pragma unroll
        for (int cc = cc0; cc < cc0 + 2; ++cc) {
            uint32_t ru[32], rg[32];
            ldtm_x32(ru, d_up + cc * 32);
            ldtm_x32(rg, d_gate + cc * 32);
            TCGEN05_WAIT_LD();
            const size_t base = (size_t)token * I + bn + cc * 32;
#pragma unroll
            for (int q = 0; q < 8; ++q) {
                float4 h4;
                float* hp = (float*)&h4;
#pragma unroll
                for (int e = 0; e < 4; ++e) {
                    const int j = q * 4 + e;
                    const float up = __uint_as_float(ru[j]);
                    const float g  = __uint_as_float(rg[j]);
                    const float a  = avg_s[cc * 32 + j];
                    const float m  = fabsf(up * a);
                    float v = 0.0f;
                    if (m >= 0.5f) v = (g / (1.0f + expf(-g))) * up;
                    if (fabsf(m - 0.5f) < FIX_DELTA) {
                        const unsigned idx = atomicAdd(&g_fix_cnt, 1u);
                        if (idx < FIX_CAP)
                            g_fix_list[idx] = ((unsigned)token << 14) | (unsigned)(bn + cc * 32 + j);
                    }
                    hp[e] = tf32_rn(v);
                }
                *(float4*)(g_t_r + base + q * 4) = h4;
            }
        }
    }
    TCGEN05_FENCE_BEFORE();
    __syncthreads();
    if (wid == 0) tmem_dealloc(tmem, 256);

#else // ---------------- fallback: FFMA pipeline (compute_103 pass) --------
    extern __shared__ char smem_raw[];
    constexpr int BK = 16, TM = 8, TN = 4, AST = 132, BST = 68;
    float* AsS = (float*)smem_raw;
    float* BuS = AsS + 2 * BK * AST;
    float* BgS = BuS + 2 * BK * BST;
#define A_AT(s,k,r) AsS[((s) * BK + (k)) * AST + (r)]
#define U_AT(s,k,r) BuS[((s) * BK + (k)) * BST + (r)]
#define G_AT(s,k,r) BgS[((s) * BK + (k)) * BST + (r)]
    const int tid = threadIdx.x;
    const int tx = tid & 15, ty = tid >> 4;
    const int row0 = ty * TM, col0 = tx * TN;
    const int lr = tid >> 2, lk = (tid & 3) * 4;
    const int bm = blockIdx.y * 128;
    const int bnBase = blockIdx.x * 128;
    const int ktiles = H / BK;
    for (int half = 0; half < 2; ++half) {
        const int bn = bnBase + half * 64;
        const float* pa0 = x  + (size_t)(bm + lr)      * H + lk;
        const float* pa1 = x  + (size_t)(bm + lr + 64) * H + lk;
        const float* pbu = wu + (size_t)(bn + lr)      * H + lk;
        const float* pbg = wg + (size_t)(bn + lr)      * H + lk;
        float accU[TM][TN] = {};
        float accG[TM][TN] = {};
        {
            float4 a0 = *(const float4*)pa0;
            float4 a1 = *(const float4*)pa1;
            float4 b0 = *(const float4*)pbu;
            float4 b1 = *(const float4*)pbg;
            float av0[4] = {a0.x, a0.y, a0.z, a0.w};
            float av1[4] = {a1.x, a1.y, a1.z, a1.w};
            float bv0[4] = {b0.x, b0.y, b0.z, b0.w};
            float bv1[4] = {b1.x, b1.y, b1.z, b1.w};
#pragma unroll
            for (int e = 0; e < 4; e++) {
                A_AT(0, lk + e, lr)      = av0[e];
                A_AT(0, lk + e, lr + 64) = av1[e];
                U_AT(0, lk + e, lr)      = bv0[e];
                G_AT(0, lk + e, lr)      = bv1[e];
            }
        }
        __syncthreads();
        for (int kt = 0; kt < ktiles; ++kt) {
            const int cur = kt & 1, nxt = cur ^ 1;
            float4 na0, na1, nbu, nbg;
            const bool more = (kt + 1 < ktiles);
            if (more) {
                const int off = (kt + 1) * BK;
                na0 = *(const float4*)(pa0 + off);
                na1 = *(const float4*)(pa1 + off);
                nbu = *(const float4*)(pbu + off);
                nbg = *(const float4*)(pbg + off);
            }
#pragma unroll
            for (int k = 0; k < BK; k++) {
                float af[TM], uf[TN], gf[TN];
#pragma unroll
                for (int i = 0; i < TM; i++) af[i] = A_AT(cur, k, row0 + i);
#pragma unroll
                for (int j = 0; j < TN; j++) {
                    uf[j] = U_AT(cur, k, col0 + j);
                    gf[j] = G_AT(cur, k, col0 + j);
                }
#pragma unroll
                for (int i = 0; i < TM; i++)
#pragma unroll
                    for (int j = 0; j < TN; j++) {
                        accU[i][j] = fmaf(af[i], uf[j], accU[i][j]);
                        accG[i][j] = fmaf(af[i], gf[j], accG[i][j]);
                    }
            }
            if (more) {
                float av0[4] = {na0.x, na0.y, na0.z, na0.w};
                float av1[4] = {na1.x, na1.y, na1.z, na1.w};
                float bv0[4] = {nbu.x, nbu.y, nbu.z, nbu.w};
                float bv1[4] = {nbg.x, nbg.y, nbg.z, nbg.w};
#pragma unroll
                for (int e = 0; e < 4; e++) {
                    A_AT(nxt, lk + e, lr)      = av0[e];
                    A_AT(nxt, lk + e, lr + 64) = av1[e];
                    U_AT(nxt, lk + e, lr)      = bv0[e];
                    G_AT(nxt, lk + e, lr)      = bv1[e];
                }
            }
            __syncthreads();
        }
#pragma unroll
        for (int j = 0; j < TN; j++) {
            const int col = bn + col0 + j;
            const float a = avg[col];
#pragma unroll
            for (int i = 0; i < TM; i++) {
                const float up = accU[i][j];
                const float g  = accG[i][j];
                float v = 0.0f;
                if (fabsf(up * a) >= 0.5f) v = (g / (1.0f + expf(-g))) * up;
                g_t_r[(size_t)(bm + row0 + i) * I + col] = v;
            }
        }
        __syncthreads();
    }
#undef A_AT
#undef U_AT
#undef G_AT
#endif
}

// ===========================================================================
// Correction: exact FFMA recompute of flagged (token, neuron) pairs.
// ===========================================================================
__global__ __launch_bounds__(256)
void fix_mask_kernel(const float* __restrict__ x, const float* __restrict__ wg,
                     const float* __restrict__ wu, const float* __restrict__ avg,
                     int H, int I)
{
    const unsigned raw = g_fix_cnt;
    const unsigned n = raw < FIX_CAP ? raw : FIX_CAP;
    const unsigned warp_g = (blockIdx.x * blockDim.x + threadIdx.x) >> 5;
    const unsigned nwarps = (gridDim.x * blockDim.x) >> 5;
    const int lane = threadIdx.x & 31;

    for (unsigned i = warp_g; i < n; i += nwarps) {
        const unsigned code = g_fix_list[i];
        const int token  = (int)(code >> 14);
        const int neuron = (int)(code & 16383u);
        const float* xr = x  + (size_t)token  * H;
        const float* ur = wu + (size_t)neuron * H;
        const float* gr = wg + (size_t)neuron * H;
        float du = 0.0f, dg = 0.0f;
        for (int k = lane * 4; k < H; k += 128) {
            const float4 xv = *(const float4*)(xr + k);
            const float4 uv = *(const float4*)(ur + k);
            const float4 gv = *(const float4*)(gr + k);
            du = fmaf(xv.x, uv.x, fmaf(xv.y, uv.y, fmaf(xv.z, uv.z, fmaf(xv.w, uv.w, du))));
            dg = fmaf(xv.x, gv.x, fmaf(xv.y, gv.y, fmaf(xv.z, gv.z, fmaf(xv.w, gv.w, dg))));
        }
#pragma unroll
        for (int o = 16; o; o >>= 1) {
            du += __shfl_xor_sync(0xFFFFFFFFu, du, o);
            dg += __shfl_xor_sync(0xFFFFFFFFu, dg, o);
        }
        if (lane == 0) {
            float v = 0.0f;
            if (fabsf(du * avg[neuron]) >= 0.5f)
                v = (dg / (1.0f + expf(-dg))) * du;
            g_t_r[(size_t)token * I + neuron] = tf32_rn(v);
        }
    }
}

// ===========================================================================
// Kernel 2: down projection. out[M,H] = t @ wd^T. 1-pass TF32.
// Tile 128 tokens x 256 H-cols, BK=32. Stage = t(16K)+wd(32K)=48K, 4 stages.
// TMEM 256 cols. Two N=128 MMAs per K-step (wd rows 0-127, 128-255).
// ===========================================================================
__global__ __launch_bounds__(256)
void down_mma(const float* __restrict__ wd, float* __restrict__ out,
              int M, int H, int I)
{
#if TC_OK
    extern __shared__ char smem[];
    const uint32_t sb = smem_u32(smem);
    constexpr uint32_t STAGE0 = 1024, SSZ = 49152;

    const int tid = threadIdx.x;
    const int wid = tid >> 5;
    const int lane = tid & 31;

    const int GX = gridDim.x;
    const int lin = blockIdx.y * GX + blockIdx.x;
    const int band = lin / (8 * GX);
    const int rr = lin - band * 8 * GX;
    const int bn = (rr >> 3) * 256;
    const int bm = (band * 8 + (rr & 7)) * 128;

    if (wid == 0) tmem_alloc(sb, 256);
    if (tid == 0)
#pragma unroll
        for (int s = 0; s < 4; ++s) mbar_init(sb + 16 + 8 * s, 1);
    __syncthreads();
    const uint32_t tmem = *(volatile uint32_t*)smem;

    const int lrow = tid >> 1;
    const int lc0  = (tid & 1) * 4;
    const int nchunks = I / 32;
    int ph[4] = {0, 0, 0, 0};

    const float* trow = g_t_r  + (size_t)(bm + lrow) * I;
    const float* wrow = g_wd_r + (size_t)(bn + tid) * I; // full 128B row per thread

    auto load_stage = [&](int kt, int s) {
        const uint32_t sa = sb + STAGE0 + (uint32_t)s * SSZ;
        const int col0 = kt * 32;
#pragma unroll
        for (int k = 0; k < 4; ++k) {
            const int c = lc0 + k;
            cp16(sa + SWZ((uint32_t)(lrow * 128 + c * 16)), trow + col0 + c * 4);
        }
#pragma unroll
        for (int k = 0; k < 8; ++k) {
            cp16(sa + 16384 + SWZ((uint32_t)(tid * 128 + k * 16)), wrow + col0 + k * 4);
        }
        CP_COMMIT();
    };

    load_stage(0, 0); load_stage(1, 1); load_stage(2, 2);

    for (int kt = 0; kt < nchunks; ++kt) {
        cp_wait_pend(nchunks - 1 - kt);
        __syncthreads();

        if (wid == 0 && elect_one()) {
            FENCE_ASYNC_SHARED();
            const uint32_t sa = sb + STAGE0 + (uint32_t)(kt & 3) * SSZ;
            const uint64_t td = sdesc(sa), wd0 = sdesc(sa + 16384);
#pragma unroll
            for (int st = 0; st < 4; ++st) {
                const uint32_t en = (kt > 0 || st > 0) ? 1u : 0u;
                const uint64_t o = (uint64_t)(st * 2);
                mma_tf32_ss(tmem,       td + o, wd0 + o,        IDESC_TF32, en);
                mma_tf32_ss(tmem + 128, td + o, wd0 + 1024 + o, IDESC_TF32, en);
            }
            mma_commit(sb + 16 + 8 * (kt & 3));
        }

        const int tgt = kt + 3;
        if (tgt < nchunks) {
            const int s = tgt & 3;
            if (tgt >= 4) { mbar_wait(sb + 16 + 8 * s, ph[s]); ph[s] ^= 1; }
            load_stage(tgt, s);
        }
    }
#pragma unroll
    for (int s = 0; s < 4; ++s) mbar_wait(sb + 16 + 8 * s, ph[s]);
    TCGEN05_FENCE_AFTER();

    {
        const int sub = wid & 3;
        const int token = bm + sub * 32 + lane;
        const int cc0 = (wid >> 2) * 4;
#pragma unroll
        for (int cc = cc0; cc < cc0 + 4; ++cc) {
            uint32_t r[32];
            ldtm_x32(r, tmem + cc * 32);
            TCGEN05_WAIT_LD();
            const size_t base = (size_t)token * H + bn + cc * 32;
#pragma unroll
            for (int q = 0; q < 8; ++q) {
                float4 v4;
                ((float*)&v4)[0] = __uint_as_float(r[q * 4 + 0]);
                ((float*)&v4)[1] = __uint_as_float(r[q * 4 + 1]);
                ((float*)&v4)[2] = __uint_as_float(r[q * 4 + 2]);
                ((float*)&v4)[3] = __uint_as_float(r[q * 4 + 3]);
                *(float4*)(out + base + q * 4) = v4;
            }
        }
    }
    TCGEN05_FENCE_BEFORE();
    __syncthreads();
    if (wid == 0) tmem_dealloc(tmem, 256);

#else // ---------------- fallback: FFMA down (two 128-col halves) ----------
    extern __shared__ char smem_raw[];
    constexpr int BK = 16, TM = 8, TN = 8, AST = 132;
    float* AsS = (float*)smem_raw;
    float* BsS = AsS + 2 * BK * AST;
#define A_AT(s,k,r) AsS[((s) * BK + (k)) * AST + (r)]
#define B_AT(s,k,r) BsS[((s) * BK + (k)) * AST + (r)]
    const int tid = threadIdx.x;
    const int tx = tid & 15, ty = tid >> 4;
    const int row0 = ty * TM, col0 = tx * TN;
    const int lr = tid >> 2, lk = (tid & 3) * 4;
    const int bm = blockIdx.y * 128;
    const int ktiles = I / BK;
    for (int half = 0; half < 2; ++half) {
        const int bn = blockIdx.x * 256 + half * 128;
        const float* pa0 = g_t_r  + (size_t)(bm + lr)      * I + lk;
        const float* pa1 = g_t_r  + (size_t)(bm + lr + 64) * I + lk;
        const float* pb0 = wd     + (size_t)(bn + lr)      * I + lk;
        const float* pb1 = wd     + (size_t)(bn + lr + 64) * I + lk;
        float acc[TM][TN] = {};
        {
            float4 a0 = *(const float4*)pa0;
            float4 a1 = *(const float4*)pa1;
            float4 b0 = *(const float4*)pb0;
            float4 b1 = *(const float4*)pb1;
            float av0[4] = {a0.x, a0.y, a0.z, a0.w};
            float av1[4] = {a1.x, a1.y, a1.z, a1.w};
            float bv0[4] = {b0.x, b0.y, b0.z, b0.w};
            float bv1[4] = {b1.x, b1.y, b1.z, b1.w};
#pragma unroll
            for (int e = 0; e < 4; e++) {
                A_AT(0, lk + e, lr)      = av0[e];
                A_AT(0, lk + e, lr + 64) = av1[e];
                B_AT(0, lk + e, lr)      = bv0[e];
                B_AT(0, lk + e, lr + 64) = bv1[e];
            }
        }
        __syncthreads();
        for (int kt = 0; kt < ktiles; ++kt) {
            const int cur = kt & 1, nxt = cur ^ 1;
            float4 na0, na1, nb0, nb1;
            const bool more = (kt + 1 < ktiles);
            if (more) {
                const int off = (kt + 1) * BK;
                na0 = *(const float4*)(pa0 + off);
                na1 = *(const float4*)(pa1 + off);
                nb0 = *(const float4*)(pb0 + off);
                nb1 = *(const float4*)(pb1 + off);
            }
#pragma unroll
            for (int k = 0; k < BK; k++) {
                float af[TM], bf[TN];
#pragma unroll
                for (int i = 0; i < TM; i++) af[i] = A_AT(cur, k, row0 + i);
#pragma unroll
                for (int j = 0; j < TN; j++) bf[j] = B_AT(cur, k, col0 + j);
#pragma unroll
                for (int i = 0; i < TM; i++)
#pragma unroll
                    for (int j = 0; j < TN; j++)
                        acc[i][j] = fmaf(af[i], bf[j], acc[i][j]);
            }
            if (more) {
                float av0[4] = {na0.x, na0.y, na0.z, na0.w};
                float av1[4] = {na1.x, na1.y, na1.z, na1.w};
                float bv0[4] = {nb0.x, nb0.y, nb0.z, nb0.w};
                float bv1[4] = {nb1.x, nb1.y, nb1.z, nb1.w};
#pragma unroll
                for (int e = 0; e < 4; e++) {
                    A_AT(nxt, lk + e, lr)      = av0[e];
                    A_AT(nxt, lk + e, lr + 64) = av1[e];
                    B_AT(nxt, lk + e, lr)      = bv0[e];
                    B_AT(nxt, lk + e, lr + 64) = bv1[e];
                }
            }
            __syncthreads();
        }
#pragma unroll
        for (int i = 0; i < TM; i++) {
            const size_t rbase = (size_t)(bm + row0 + i) * H + bn + col0;
#pragma unroll
            for (int j = 0; j < TN; j++) out[rbase + j] = acc[i][j];
        }
        __syncthreads();
    }
#undef A_AT
#undef B_AT
#endif
}

// ---------------------------------------------------------------------------
// Launch: pre-round x4 -> reset -> upgate(+flag) -> fix -> down
// ---------------------------------------------------------------------------
extern "C" void kernel_launch(void* const* d_in, const int* in_sizes, int n_in,
                              void* d_out, int out_size)
{
    const float* x   = (const float*)d_in[0];
    const float* wg  = (const float*)d_in[1];
    const float* wu  = (const float*)d_in[2];
    const float* wd  = (const float*)d_in[3];
    const float* avg = (const float*)d_in[4];
    float* out = (float*)d_out;

    const int I = in_sizes[4];            // 14336
    const int H = in_sizes[3] / I;        // 4096
    const int M = in_sizes[0] / H;        // 8192

    cudaFuncSetAttribute(upgate_mma, cudaFuncAttributeMaxDynamicSharedMemorySize, SMEM_BYTES);
    cudaFuncSetAttribute(down_mma,   cudaFuncAttributeMaxDynamicSharedMemorySize, SMEM_BYTES);

    float* xr; float* wur; float* wgr; float* wdr;
    cudaGetSymbolAddress((void**)&xr,  g_x_r);
    cudaGetSymbolAddress((void**)&wur, g_wu_r);
    cudaGetSymbolAddress((void**)&wgr, g_wg_r);
    cudaGetSymbolAddress((void**)&wdr, g_wd_r);

    round_tf32_kernel<<<2048, 256>>>(xr,  x,  (long long)M * H);
    round_tf32_kernel<<<2048, 256>>>(wur, wu, (long long)I * H);
    round_tf32_kernel<<<2048, 256>>>(wgr, wg, (long long)I * H);
    round_tf32_kernel<<<2048, 256>>>(wdr, wd, (long long)H * I);
    reset_fix_cnt<<<1, 32>>>();

    dim3 g1(I / 128, M / 128);            // 112 x 64
    upgate_mma<<<g1, 256, SMEM_BYTES>>>(x, wg, wu, avg, M, H, I);

    fix_mask_kernel<<<1024, 256>>>(x, wg, wu, avg, H, I);

    dim3 g2(H / 256, M / 128);            // 16 x 64
    down_mma<<<g2, 256, SMEM_BYTES>>>(wd, out, M, H, I);
}

// round 6
// speedup vs baseline: 10.4244x; 2.0231x over previous
#include <cuda_runtime.h>
#include <cuda.h>
#include <math.h>
#include <stdint.h>

// ---------------------------------------------------------------------------
// Feature detection: tcgen05/TMA-tensor are arch-SPECIFIC (sm_103a / sm_100a).
// ---------------------------------------------------------------------------
#ifdef __CUDA_ARCH_HAS_FEATURE__
#define TC_FEAT_103 __CUDA_ARCH_HAS_FEATURE__(SM103_ALL)
#define TC_FEAT_100 __CUDA_ARCH_HAS_FEATURE__(SM100_ALL)
#else
#define TC_FEAT_103 0
#define TC_FEAT_100 0
#endif
#if defined(__CUDA_ARCH__) && (TC_FEAT_103 || TC_FEAT_100 || \
    defined(__CUDA_ARCH_FEAT_SM103_ALL) || defined(__CUDA_ARCH_FEAT_SM100_ALL))
#define TC_OK 1
#else
#define TC_OK 0
#endif

// ---------------------------------------------------------------------------
// Global scratch (static; no allocations allowed).
// ---------------------------------------------------------------------------
static __device__ float g_t_r [117440512ull]; // 8192*14336 (tf32-rounded t)
static __device__ float g_x_r [33554432ull];  // 8192*4096
static __device__ float g_wu_r[58720256ull];  // 14336*4096
static __device__ float g_wg_r[58720256ull];
static __device__ float g_wd_r[58720256ull];  // 4096*14336
static constexpr unsigned FIX_CAP = 8388608u;
static __device__ unsigned g_fix_cnt;
static __device__ unsigned g_fix_list[FIX_CAP];

#define FIX_DELTA 2.0e-3f
static constexpr int SMEM_UP   = 2048 + 2 * 81920; // 165888
static constexpr int SMEM_DOWN = 1024 + 4 * 49152; // 197632

// tf32 round (sm_80+, safe on every compile pass)
__device__ __forceinline__ float tf32_rn(float a) {
    uint32_t r;
    asm("cvt.rna.tf32.f32 %0, %1;" : "=r"(r) : "f"(a));
    return __uint_as_float(r);
}

#if TC_OK
// ===========================================================================
// sm_103a helpers
// ===========================================================================
__device__ __forceinline__ uint32_t smem_u32(const void* p) {
    uint32_t a;
    asm("{ .reg .u64 t; cvta.to.shared.u64 t, %1; cvt.u32.u64 %0, t; }"
        : "=r"(a) : "l"(p));
    return a;
}
__device__ __forceinline__ uint32_t elect_one() {
    uint32_t p;
    asm volatile("{ .reg .pred p; elect.sync _|p, 0xFFFFFFFF; selp.b32 %0, 1, 0, p; }"
                 : "=r"(p));
    return p;
}
__device__ __forceinline__ void mbar_init(uint32_t addr, uint32_t cnt) {
    asm volatile("mbarrier.init.shared.b64 [%0], %1;" :: "r"(addr), "r"(cnt) : "memory");
}
__device__ __forceinline__ void mbar_wait(uint32_t mbar, int parity) {
    uint32_t done;
    asm volatile("{\n\t.reg .pred p;\n\t"
                 "mbarrier.try_wait.parity.acquire.cta.shared::cta.b64 p, [%1], %2;\n\t"
                 "selp.b32 %0, 1, 0, p;\n\t}"
                 : "=r"(done) : "r"(mbar), "r"((uint32_t)parity) : "memory");
    while (!done) {
        asm volatile("{\n\t.reg .pred p;\n\t"
                     "mbarrier.try_wait.parity.acquire.cta.shared::cta.b64 p, [%1], %2, 0x989680;\n\t"
                     "selp.b32 %0, 1, 0, p;\n\t}"
                     : "=r"(done) : "r"(mbar), "r"((uint32_t)parity) : "memory");
    }
}
__device__ __forceinline__ void mbar_expect_tx(uint32_t mbar, uint32_t bytes) {
    asm volatile("mbarrier.arrive.expect_tx.shared.b64 _, [%0], %1;"
                 :: "r"(mbar), "r"(bytes) : "memory");
}
__device__ __forceinline__ void tma2d(uint32_t dst, const CUtensorMap* map,
                                      int cx, int cy, uint32_t mbar) {
    asm volatile("cp.async.bulk.tensor.2d.shared::cta.global.tile.mbarrier::complete_tx::bytes "
                 "[%0], [%1, {%2, %3}], [%4];"
                 :: "r"(dst), "l"(map), "r"(cx), "r"(cy), "r"(mbar) : "memory");
}
__device__ __forceinline__ void tmem_alloc(uint32_t smem_dst, uint32_t ncols) {
    asm volatile("tcgen05.alloc.cta_group::1.sync.aligned.shared::cta.b32 [%0], %1;"
                 :: "r"(smem_dst), "r"(ncols) : "memory");
}
__device__ __forceinline__ void tmem_dealloc(uint32_t tmem, uint32_t ncols) {
    asm volatile("tcgen05.relinquish_alloc_permit.cta_group::1.sync.aligned;");
    asm volatile("tcgen05.dealloc.cta_group::1.sync.aligned.b32 %0, %1;" :: "r"(tmem), "r"(ncols));
}
__device__ __forceinline__ void mma_commit(uint32_t mbar) {
    asm volatile("tcgen05.commit.cta_group::1.mbarrier::arrive::one.shared::cluster.b64 [%0];"
                 :: "r"(mbar) : "memory");
}
__device__ __forceinline__ void mma_tf32_ss(uint32_t d, uint64_t a_desc, uint64_t b_desc,
                                            uint32_t idesc, uint32_t en) {
    asm volatile("{\n\t.reg .pred p;\n\tsetp.ne.u32 p, %4, 0;\n\t"
                 "tcgen05.mma.cta_group::1.kind::tf32 [%0], %1, %2, %3, p;\n\t}"
                 :: "r"(d), "l"(a_desc), "l"(b_desc), "r"(idesc), "r"(en) : "memory");
}
// SW128 K-major descriptor: LBO=1, SBO=64, layout=2, version=1.
__device__ __forceinline__ uint64_t sdesc(uint32_t addr) {
    constexpr uint64_t BASE = (2ull << 61) | (1ull << 46) | (64ull << 32) | (1ull << 16);
    return BASE | ((uint64_t)(addr >> 4) & 0x3FFFull);
}
__device__ __forceinline__ void ldtm_x32(uint32_t* r, uint32_t addr) {
    asm volatile(
        "tcgen05.ld.sync.aligned.32x32b.x32.b32 "
        "{%0, %1, %2, %3, %4, %5, %6, %7, "
        " %8, %9, %10, %11, %12, %13, %14, %15, "
        " %16, %17, %18, %19, %20, %21, %22, %23, "
        " %24, %25, %26, %27, %28, %29, %30, %31}, [%32];"
        : "=r"(r[0]),  "=r"(r[1]),  "=r"(r[2]),  "=r"(r[3]),
          "=r"(r[4]),  "=r"(r[5]),  "=r"(r[6]),  "=r"(r[7]),
          "=r"(r[8]),  "=r"(r[9]),  "=r"(r[10]), "=r"(r[11]),
          "=r"(r[12]), "=r"(r[13]), "=r"(r[14]), "=r"(r[15]),
          "=r"(r[16]), "=r"(r[17]), "=r"(r[18]), "=r"(r[19]),
          "=r"(r[20]), "=r"(r[21]), "=r"(r[22]), "=r"(r[23]),
          "=r"(r[24]), "=r"(r[25]), "=r"(r[26]), "=r"(r[27]),
          "=r"(r[28]), "=r"(r[29]), "=r"(r[30]), "=r"(r[31])
        : "r"(addr));
}
#define TCGEN05_WAIT_LD()      asm volatile("tcgen05.wait::ld.sync.aligned;" ::: "memory")
#define FENCE_ASYNC_SHARED()   asm volatile("fence.proxy.async.shared::cta;" ::: "memory")
#define TCGEN05_FENCE_AFTER()  asm volatile("tcgen05.fence::after_thread_sync;" ::: "memory")
#define TCGEN05_FENCE_BEFORE() asm volatile("tcgen05.fence::before_thread_sync;" ::: "memory")

// idesc: c=F32, a=b=TF32, K-major, N=128, M=128
static constexpr uint32_t IDESC_TF32 =
    (1u << 4) | (2u << 7) | (2u << 10) | ((128u / 8u) << 17) | ((128u / 16u) << 24);
#endif // TC_OK

// ===========================================================================
// Pre-round + reset
// ===========================================================================
__global__ void round_tf32_kernel(float* __restrict__ dst, const float* __restrict__ src,
                                  long long n) {
    long long i = ((long long)blockIdx.x * blockDim.x + threadIdx.x) * 4;
    const long long stride = (long long)gridDim.x * blockDim.x * 4;
    for (; i < n; i += stride) {
        float4 v = *(const float4*)(src + i);
        v.x = tf32_rn(v.x); v.y = tf32_rn(v.y);
        v.z = tf32_rn(v.z); v.w = tf32_rn(v.w);
        *(float4*)(dst + i) = v;
    }
}
__global__ void reset_fix_cnt() {
    if (threadIdx.x == 0 && blockIdx.x == 0) g_fix_cnt = 0;
}

// ===========================================================================
// Kernel 1: fused up+gate. 1-pass TF32, TMA 2-stage pipeline, BN=256.
// Stage = x(16K) + wu(32K) + wg(32K) = 80KB. TMEM: up [0,256), gate [256,512).
// ===========================================================================
__global__ __launch_bounds__(256)
void upgate_mma(const __grid_constant__ CUtensorMap mx,
                const __grid_constant__ CUtensorMap mu,
                const __grid_constant__ CUtensorMap mg,
                const float* __restrict__ x, const float* __restrict__ wg,
                const float* __restrict__ wu, const float* __restrict__ avg,
                int M, int H, int I)
{
#if TC_OK
    extern __shared__ __align__(1024) char smem[];
    const uint32_t sb = smem_u32(smem);
    float* avg_s = (float*)(smem + 128);
    constexpr uint32_t STAGE0 = 2048, SSZ = 81920;

    const int tid = threadIdx.x;
    const int wid = tid >> 5;
    const int lane = tid & 31;

    // Supertile remap: bands of 8 bm, n-major inside a band.
    const int GX = gridDim.x; // 56
    const int lin = blockIdx.y * GX + blockIdx.x;
    const int band = lin / (8 * GX);
    const int rr = lin - band * 8 * GX;
    const int bn = (rr >> 3) * 256;
    const int bm = (band * 8 + (rr & 7)) * 128;

    if (wid == 0) tmem_alloc(sb, 512);
    if (tid == 0) {
#pragma unroll
        for (int s = 0; s < 2; ++s) { mbar_init(sb + 16 + 8 * s, 1); mbar_init(sb + 64 + 8 * s, 1); }
        FENCE_ASYNC_SHARED();
    }
    avg_s[tid] = avg[bn + tid];
    __syncthreads();
    const uint32_t tmem = *(volatile uint32_t*)smem;
    const int nchunks = H / 32;

    if (wid == 0) {
        int phf[2] = {0, 0}, phd[2] = {0, 0};
        const uint32_t e1 = elect_one();
        if (e1) {
#pragma unroll
            for (int s = 0; s < 2; ++s) {
                const uint32_t sa = sb + STAGE0 + (uint32_t)s * SSZ;
                mbar_expect_tx(sb + 16 + 8 * s, 81920);
                tma2d(sa,         &mx, s * 32, bm, sb + 16 + 8 * s);
                tma2d(sa + 16384, &mu, s * 32, bn, sb + 16 + 8 * s);
                tma2d(sa + 49152, &mg, s * 32, bn, sb + 16 + 8 * s);
            }
        }
        for (int kt = 0; kt < nchunks; ++kt) {
            const int s = kt & 1;
            mbar_wait(sb + 16 + 8 * s, phf[s]); phf[s] ^= 1;
            if (e1) {
                const uint32_t sa = sb + STAGE0 + (uint32_t)s * SSZ;
                const uint64_t xd  = sdesc(sa);
                const uint64_t ud0 = sdesc(sa + 16384), ud1 = sdesc(sa + 32768);
                const uint64_t gd0 = sdesc(sa + 49152), gd1 = sdesc(sa + 65536);
#pragma unroll
                for (int st = 0; st < 4; ++st) {
                    const uint32_t en = (kt > 0 || st > 0) ? 1u : 0u;
                    const uint64_t o = (uint64_t)(st * 2);
                    mma_tf32_ss(tmem,       xd + o, ud0 + o, IDESC_TF32, en);
                    mma_tf32_ss(tmem + 128, xd + o, ud1 + o, IDESC_TF32, en);
                    mma_tf32_ss(tmem + 256, xd + o, gd0 + o, IDESC_TF32, en);
                    mma_tf32_ss(tmem + 384, xd + o, gd1 + o, IDESC_TF32, en);
                }
                mma_commit(sb + 64 + 8 * s);
            }
            const int tgt = kt + 2;
            if (tgt < nchunks) {
                mbar_wait(sb + 64 + 8 * s, phd[s]); phd[s] ^= 1;
                if (e1) {
                    const uint32_t sa = sb + STAGE0 + (uint32_t)s * SSZ;
                    mbar_expect_tx(sb + 16 + 8 * s, 81920);
                    tma2d(sa,         &mx, tgt * 32, bm, sb + 16 + 8 * s);
                    tma2d(sa + 16384, &mu, tgt * 32, bn, sb + 16 + 8 * s);
                    tma2d(sa + 49152, &mg, tgt * 32, bn, sb + 16 + 8 * s);
                }
            }
        }
#pragma unroll
        for (int s = 0; s < 2; ++s) mbar_wait(sb + 64 + 8 * s, phd[s]);
    }
    __syncthreads();
    TCGEN05_FENCE_AFTER();

    // Epilogue: mask + silu + flag + write t_r.
    {
        const int sub = wid & 3;
        const int token = bm + sub * 32 + lane;
        const int half = wid >> 2;
#pragma unroll
        for (int q = 0; q < 4; ++q) {
            const int cc = half * 4 + q;           // 0..7 -> N cols cc*32..cc*32+31
            uint32_t ru[32], rg[32];
            ldtm_x32(ru, tmem + cc * 32);
            ldtm_x32(rg, tmem + 256 + cc * 32);
            TCGEN05_WAIT_LD();
            const size_t base = (size_t)token * I + bn + cc * 32;
#pragma unroll
            for (int qq = 0; qq < 8; ++qq) {
                float4 h4;
                float* hp = (float*)&h4;
#pragma unroll
                for (int e = 0; e < 4; ++e) {
                    const int j = qq * 4 + e;
                    const float up = __uint_as_float(ru[j]);
                    const float g  = __uint_as_float(rg[j]);
                    const float a  = avg_s[cc * 32 + j];
                    const float m  = fabsf(up * a);
                    float v = 0.0f;
                    if (m >= 0.5f) v = (g / (1.0f + expf(-g))) * up;
                    if (fabsf(m - 0.5f) < FIX_DELTA) {
                        const unsigned idx = atomicAdd(&g_fix_cnt, 1u);
                        if (idx < FIX_CAP)
                            g_fix_list[idx] = ((unsigned)token << 14) | (unsigned)(bn + cc * 32 + j);
                    }
                    hp[e] = tf32_rn(v);
                }
                *(float4*)(g_t_r + base + qq * 4) = h4;
            }
        }
    }
    TCGEN05_FENCE_BEFORE();
    __syncthreads();
    if (wid == 0) tmem_dealloc(tmem, 512);

#else // ---------------- fallback: FFMA pipeline (compute_103 pass) --------
    extern __shared__ char smem_raw[];
    constexpr int BK = 16, TM = 8, TN = 4, AST = 132, BST = 68;
    float* AsS = (float*)smem_raw;
    float* BuS = AsS + 2 * BK * AST;
    float* BgS = BuS + 2 * BK * BST;
#define A_AT(s,k,r) AsS[((s) * BK + (k)) * AST + (r)]
#define U_AT(s,k,r) BuS[((s) * BK + (k)) * BST + (r)]
#define G_AT(s,k,r) BgS[((s) * BK + (k)) * BST + (r)]
    const int tid = threadIdx.x;
    const int tx = tid & 15, ty = tid >> 4;
    const int row0 = ty * TM, col0 = tx * TN;
    const int lr = tid >> 2, lk = (tid & 3) * 4;
    const int bm = blockIdx.y * 128;
    const int bnBase = blockIdx.x * 256;
    const int ktiles = H / BK;
    for (int half = 0; half < 4; ++half) {
        const int bn = bnBase + half * 64;
        const float* pa0 = x  + (size_t)(bm + lr)      * H + lk;
        const float* pa1 = x  + (size_t)(bm + lr + 64) * H + lk;
        const float* pbu = wu + (size_t)(bn + lr)      * H + lk;
        const float* pbg = wg + (size_t)(bn + lr)      * H + lk;
        float accU[TM][TN] = {};
        float accG[TM][TN] = {};
        {
            float4 a0 = *(const float4*)pa0;
            float4 a1 = *(const float4*)pa1;
            float4 b0 = *(const float4*)pbu;
            float4 b1 = *(const float4*)pbg;
            float av0[4] = {a0.x, a0.y, a0.z, a0.w};
            float av1[4] = {a1.x, a1.y, a1.z, a1.w};
            float bv0[4] = {b0.x, b0.y, b0.z, b0.w};
            float bv1[4] = {b1.x, b1.y, b1.z, b1.w};
#pragma unroll
            for (int e = 0; e < 4; e++) {
                A_AT(0, lk + e, lr)      = av0[e];
                A_AT(0, lk + e, lr + 64) = av1[e];
                U_AT(0, lk + e, lr)      = bv0[e];
                G_AT(0, lk + e, lr)      = bv1[e];
            }
        }
        __syncthreads();
        for (int kt = 0; kt < ktiles; ++kt) {
            const int cur = kt & 1, nxt = cur ^ 1;
            float4 na0, na1, nbu, nbg;
            const bool more = (kt + 1 < ktiles);
            if (more) {
                const int off = (kt + 1) * BK;
                na0 = *(const float4*)(pa0 + off);
                na1 = *(const float4*)(pa1 + off);
                nbu = *(const float4*)(pbu + off);
                nbg = *(const float4*)(pbg + off);
            }
#pragma unroll
            for (int k = 0; k < BK; k++) {
                float af[TM], uf[TN], gf[TN];
#pragma unroll
                for (int i = 0; i < TM; i++) af[i] = A_AT(cur, k, row0 + i);
#pragma unroll
                for (int j = 0; j < TN; j++) {
                    uf[j] = U_AT(cur, k, col0 + j);
                    gf[j] = G_AT(cur, k, col0 + j);
                }
#pragma unroll
                for (int i = 0; i < TM; i++)
#pragma unroll
                    for (int j = 0; j < TN; j++) {
                        accU[i][j] = fmaf(af[i], uf[j], accU[i][j]);
                        accG[i][j] = fmaf(af[i], gf[j], accG[i][j]);
                    }
            }
            if (more) {
                float av0[4] = {na0.x, na0.y, na0.z, na0.w};
                float av1[4] = {na1.x, na1.y, na1.z, na1.w};
                float bv0[4] = {nbu.x, nbu.y, nbu.z, nbu.w};
                float bv1[4] = {nbg.x, nbg.y, nbg.z, nbg.w};
#pragma unroll
                for (int e = 0; e < 4; e++) {
                    A_AT(nxt, lk + e, lr)      = av0[e];
                    A_AT(nxt, lk + e, lr + 64) = av1[e];
                    U_AT(nxt, lk + e, lr)      = bv0[e];
                    G_AT(nxt, lk + e, lr)      = bv1[e];
                }
            }
            __syncthreads();
        }
#pragma unroll
        for (int j = 0; j < TN; j++) {
            const int col = bn + col0 + j;
            const float a = avg[col];
#pragma unroll
            for (int i = 0; i < TM; i++) {
                const float up = accU[i][j];
                const float g  = accG[i][j];
                float v = 0.0f;
                if (fabsf(up * a) >= 0.5f) v = (g / (1.0f + expf(-g))) * up;
                g_t_r[(size_t)(bm + row0 + i) * I + col] = v;
            }
        }
        __syncthreads();
    }
#undef A_AT
#undef U_AT
#undef G_AT
#endif
}

// ===========================================================================
// Correction: exact FFMA recompute of flagged (token, neuron) pairs.
// ===========================================================================
__global__ __launch_bounds__(256)
void fix_mask_kernel(const float* __restrict__ x, const float* __restrict__ wg,
                     const float* __restrict__ wu, const float* __restrict__ avg,
                     int H, int I)
{
    const unsigned raw = g_fix_cnt;
    const unsigned n = raw < FIX_CAP ? raw : FIX_CAP;
    const unsigned warp_g = (blockIdx.x * blockDim.x + threadIdx.x) >> 5;
    const unsigned nwarps = (gridDim.x * blockDim.x) >> 5;
    const int lane = threadIdx.x & 31;

    for (unsigned i = warp_g; i < n; i += nwarps) {
        const unsigned code = g_fix_list[i];
        const int token  = (int)(code >> 14);
        const int neuron = (int)(code & 16383u);
        const float* xr = x  + (size_t)token  * H;
        const float* ur = wu + (size_t)neuron * H;
        const float* gr = wg + (size_t)neuron * H;
        float du = 0.0f, dg = 0.0f;
        for (int k = lane * 4; k < H; k += 128) {
            const float4 xv = *(const float4*)(xr + k);
            const float4 uv = *(const float4*)(ur + k);
            const float4 gv = *(const float4*)(gr + k);
            du = fmaf(xv.x, uv.x, fmaf(xv.y, uv.y, fmaf(xv.z, uv.z, fmaf(xv.w, uv.w, du))));
            dg = fmaf(xv.x, gv.x, fmaf(xv.y, gv.y, fmaf(xv.z, gv.z, fmaf(xv.w, gv.w, dg))));
        }
#pragma unroll
        for (int o = 16; o; o >>= 1) {
            du += __shfl_xor_sync(0xFFFFFFFFu, du, o);
            dg += __shfl_xor_sync(0xFFFFFFFFu, dg, o);
        }
        if (lane == 0) {
            float v = 0.0f;
            if (fabsf(du * avg[neuron]) >= 0.5f)
                v = (dg / (1.0f + expf(-dg))) * du;
            g_t_r[(size_t)token * I + neuron] = tf32_rn(v);
        }
    }
}

// ===========================================================================
// Kernel 2: down projection, out[M,H] = t @ wd^T. TMA 4-stage, BN=256.
// Stage = t(16K) + wd(32K) = 48KB.
// ===========================================================================
__global__ __launch_bounds__(256)
void down_mma(const __grid_constant__ CUtensorMap mt,
              const __grid_constant__ CUtensorMap mw,
              const float* __restrict__ wd, float* __restrict__ out,
              int M, int H, int I)
{
#if TC_OK
    extern __shared__ __align__(1024) char smem[];
    const uint32_t sb = smem_u32(smem);
    constexpr uint32_t STAGE0 = 1024, SSZ = 49152;

    const int tid = threadIdx.x;
    const int wid = tid >> 5;
    const int lane = tid & 31;

    const int GX = gridDim.x; // 16
    const int lin = blockIdx.y * GX + blockIdx.x;
    const int band = lin / (8 * GX);
    const int rr = lin - band * 8 * GX;
    const int bn = (rr >> 3) * 256;
    const int bm = (band * 8 + (rr & 7)) * 128;

    if (wid == 0) tmem_alloc(sb, 256);
    if (tid == 0) {
#pragma unroll
        for (int s = 0; s < 4; ++s) { mbar_init(sb + 16 + 8 * s, 1); mbar_init(sb + 64 + 8 * s, 1); }
        FENCE_ASYNC_SHARED();
    }
    __syncthreads();
    const uint32_t tmem = *(volatile uint32_t*)smem;
    const int nchunks = I / 32;

    if (wid == 0) {
        int phf[4] = {0, 0, 0, 0}, phd[4] = {0, 0, 0, 0};
        const uint32_t e1 = elect_one();
        if (e1) {
#pragma unroll
            for (int s = 0; s < 4; ++s) {
                const uint32_t sa = sb + STAGE0 + (uint32_t)s * SSZ;
                mbar_expect_tx(sb + 16 + 8 * s, 49152);
                tma2d(sa,         &mt, s * 32, bm, sb + 16 + 8 * s);
                tma2d(sa + 16384, &mw, s * 32, bn, sb + 16 + 8 * s);
            }
        }
        for (int kt = 0; kt < nchunks; ++kt) {
            const int s = kt & 3;
            mbar_wait(sb + 16 + 8 * s, phf[s]); phf[s] ^= 1;
            if (e1) {
                const uint32_t sa = sb + STAGE0 + (uint32_t)s * SSZ;
                const uint64_t td = sdesc(sa);
                const uint64_t w0 = sdesc(sa + 16384), w1 = sdesc(sa + 32768);
#pragma unroll
                for (int st = 0; st < 4; ++st) {
                    const uint32_t en = (kt > 0 || st > 0) ? 1u : 0u;
                    const uint64_t o = (uint64_t)(st * 2);
                    mma_tf32_ss(tmem,       td + o, w0 + o, IDESC_TF32, en);
                    mma_tf32_ss(tmem + 128, td + o, w1 + o, IDESC_TF32, en);
                }
                mma_commit(sb + 64 + 8 * s);
            }
            const int tgt = kt + 4;
            if (tgt < nchunks) {
                mbar_wait(sb + 64 + 8 * s, phd[s]); phd[s] ^= 1;
                if (e1) {
                    const uint32_t sa = sb + STAGE0 + (uint32_t)s * SSZ;
                    mbar_expect_tx(sb + 16 + 8 * s, 49152);
                    tma2d(sa,         &mt, tgt * 32, bm, sb + 16 + 8 * s);
                    tma2d(sa + 16384, &mw, tgt * 32, bn, sb + 16 + 8 * s);
                }
            }
        }
#pragma unroll
        for (int s = 0; s < 4; ++s) mbar_wait(sb + 64 + 8 * s, phd[s]);
    }
    __syncthreads();
    TCGEN05_FENCE_AFTER();

    {
        const int sub = wid & 3;
        const int token = bm + sub * 32 + lane;
        const int cc0 = (wid >> 2) * 4;
#pragma unroll
        for (int cc = cc0; cc < cc0 + 4; ++cc) {
            uint32_t r[32];
            ldtm_x32(r, tmem + cc * 32);
            TCGEN05_WAIT_LD();
            const size_t base = (size_t)token * H + bn + cc * 32;
#pragma unroll
            for (int q = 0; q < 8; ++q) {
                float4 v4;
                ((float*)&v4)[0] = __uint_as_float(r[q * 4 + 0]);
                ((float*)&v4)[1] = __uint_as_float(r[q * 4 + 1]);
                ((float*)&v4)[2] = __uint_as_float(r[q * 4 + 2]);
                ((float*)&v4)[3] = __uint_as_float(r[q * 4 + 3]);
                *(float4*)(out + base + q * 4) = v4;
            }
        }
    }
    TCGEN05_FENCE_BEFORE();
    __syncthreads();
    if (wid == 0) tmem_dealloc(tmem, 256);

#else // ---------------- fallback: FFMA down (two 128-col halves) ----------
    extern __shared__ char smem_raw[];
    constexpr int BK = 16, TM = 8, TN = 8, AST = 132;
    float* AsS = (float*)smem_raw;
    float* BsS = AsS + 2 * BK * AST;
#define A_AT(s,k,r) AsS[((s) * BK + (k)) * AST + (r)]
#define B_AT(s,k,r) BsS[((s) * BK + (k)) * AST + (r)]
    const int tid = threadIdx.x;
    const int tx = tid & 15, ty = tid >> 4;
    const int row0 = ty * TM, col0 = tx * TN;
    const int lr = tid >> 2, lk = (tid & 3) * 4;
    const int bm = blockIdx.y * 128;
    const int ktiles = I / BK;
    for (int half = 0; half < 2; ++half) {
        const int bn = blockIdx.x * 256 + half * 128;
        const float* pa0 = g_t_r + (size_t)(bm + lr)      * I + lk;
        const float* pa1 = g_t_r + (size_t)(bm + lr + 64) * I + lk;
        const float* pb0 = wd    + (size_t)(bn + lr)      * I + lk;
        const float* pb1 = wd    + (size_t)(bn + lr + 64) * I + lk;
        float acc[TM][TN] = {};
        {
            float4 a0 = *(const float4*)pa0;
            float4 a1 = *(const float4*)pa1;
            float4 b0 = *(const float4*)pb0;
            float4 b1 = *(const float4*)pb1;
            float av0[4] = {a0.x, a0.y, a0.z, a0.w};
            float av1[4] = {a1.x, a1.y, a1.z, a1.w};
            float bv0[4] = {b0.x, b0.y, b0.z, b0.w};
            float bv1[4] = {b1.x, b1.y, b1.z, b1.w};
#pragma unroll
            for (int e = 0; e < 4; e++) {
                A_AT(0, lk + e, lr)      = av0[e];
                A_AT(0, lk + e, lr + 64) = av1[e];
                B_AT(0, lk + e, lr)      = bv0[e];
                B_AT(0, lk + e, lr + 64) = bv1[e];
            }
        }
        __syncthreads();
        for (int kt = 0; kt < ktiles; ++kt) {
            const int cur = kt & 1, nxt = cur ^ 1;
            float4 na0, na1, nb0, nb1;
            const bool more = (kt + 1 < ktiles);
            if (more) {
                const int off = (kt + 1) * BK;
                na0 = *(const float4*)(pa0 + off);
                na1 = *(const float4*)(pa1 + off);
                nb0 = *(const float4*)(pb0 + off);
                nb1 = *(const float4*)(pb1 + off);
            }
#pragma unroll
            for (int k = 0; k < BK; k++) {
                float af[TM], bf[TN];
#pragma unroll
                for (int i = 0; i < TM; i++) af[i] = A_AT(cur, k, row0 + i);
#pragma unroll
                for (int j = 0; j < TN; j++) bf[j] = B_AT(cur, k, col0 + j);
#pragma unroll
                for (int i = 0; i < TM; i++)
#pragma unroll
                    for (int j = 0; j < TN; j++)
                        acc[i][j] = fmaf(af[i], bf[j], acc[i][j]);
            }
            if (more) {
                float av0[4] = {na0.x, na0.y, na0.z, na0.w};
                float av1[4] = {na1.x, na1.y, na1.z, na1.w};
                float bv0[4] = {nb0.x, nb0.y, nb0.z, nb0.w};
                float bv1[4] = {nb1.x, nb1.y, nb1.z, nb1.w};
#pragma unroll
                for (int e = 0; e < 4; e++) {
                    A_AT(nxt, lk + e, lr)      = av0[e];
                    A_AT(nxt, lk + e, lr + 64) = av1[e];
                    B_AT(nxt, lk + e, lr)      = bv0[e];
                    B_AT(nxt, lk + e, lr + 64) = bv1[e];
                }
            }
            __syncthreads();
        }
#pragma unroll
        for (int i = 0; i < TM; i++) {
            const size_t rbase = (size_t)(bm + row0 + i) * H + bn + col0;
#pragma unroll
            for (int j = 0; j < TN; j++) out[rbase + j] = acc[i][j];
        }
        __syncthreads();
    }
#undef A_AT
#undef B_AT
#endif
}

// ---------------------------------------------------------------------------
// Launch: pre-round -> reset -> upgate(+flag) -> fix -> down
// ---------------------------------------------------------------------------
typedef CUresult (CUDAAPI *EncodeFn)(CUtensorMap*, CUtensorMapDataType, cuuint32_t, void*,
    const cuuint64_t*, const cuuint64_t*, const cuuint32_t*, const cuuint32_t*,
    CUtensorMapInterleave, CUtensorMapSwizzle, CUtensorMapL2promotion, CUtensorMapFloatOOBfill);

extern "C" void kernel_launch(void* const* d_in, const int* in_sizes, int n_in,
                              void* d_out, int out_size)
{
    const float* x   = (const float*)d_in[0];
    const float* wg  = (const float*)d_in[1];
    const float* wu  = (const float*)d_in[2];
    const float* wd  = (const float*)d_in[3];
    const float* avg = (const float*)d_in[4];
    float* out = (float*)d_out;

    const int I = in_sizes[4];            // 14336
    const int H = in_sizes[3] / I;        // 4096
    const int M = in_sizes[0] / H;        // 8192

    cudaFuncSetAttribute(upgate_mma, cudaFuncAttributeMaxDynamicSharedMemorySize, SMEM_UP);
    cudaFuncSetAttribute(down_mma,   cudaFuncAttributeMaxDynamicSharedMemorySize, SMEM_DOWN);

    float *xr, *wur, *wgr, *wdr, *tr;
    cudaGetSymbolAddress((void**)&xr,  g_x_r);
    cudaGetSymbolAddress((void**)&wur, g_wu_r);
    cudaGetSymbolAddress((void**)&wgr, g_wg_r);
    cudaGetSymbolAddress((void**)&wdr, g_wd_r);
    cudaGetSymbolAddress((void**)&tr,  g_t_r);

    // Tensor maps (driver entry point; no -lcuda needed).
    static EncodeFn enc = nullptr;
    if (!enc) {
        void* fp = nullptr;
        cudaDriverEntryPointQueryResult qr;
        cudaGetDriverEntryPoint("cuTensorMapEncodeTiled", &fp, cudaEnableDefault, &qr);
        enc = (EncodeFn)fp;
    }
    CUtensorMap mx, mu, mg, mt, mw;
    auto mk = [&](CUtensorMap* m, void* ptr, unsigned long long inner,
                  unsigned long long rows, unsigned boxRows) {
        cuuint64_t dims[2]    = {inner, rows};
        cuuint64_t strides[1] = {inner * 4};
        cuuint32_t box[2]     = {32u, boxRows};
        cuuint32_t es[2]      = {1u, 1u};
        enc(m, CU_TENSOR_MAP_DATA_TYPE_FLOAT32, 2, ptr, dims, strides, box, es,
            CU_TENSOR_MAP_INTERLEAVE_NONE, CU_TENSOR_MAP_SWIZZLE_128B,
            CU_TENSOR_MAP_L2_PROMOTION_L2_128B, CU_TENSOR_MAP_FLOAT_OOB_FILL_NONE);
    };
    mk(&mx, xr,  (unsigned long long)H, (unsigned long long)M, 128u);
    mk(&mu, wur, (unsigned long long)H, (unsigned long long)I, 256u);
    mk(&mg, wgr, (unsigned long long)H, (unsigned long long)I, 256u);
    mk(&mt, tr,  (unsigned long long)I, (unsigned long long)M, 128u);
    mk(&mw, wdr, (unsigned long long)I, (unsigned long long)H, 256u);

    round_tf32_kernel<<<2048, 256>>>(xr,  x,  (long long)M * H);
    round_tf32_kernel<<<2048, 256>>>(wur, wu, (long long)I * H);
    round_tf32_kernel<<<2048, 256>>>(wgr, wg, (long long)I * H);
    round_tf32_kernel<<<2048, 256>>>(wdr, wd, (long long)H * I);
    reset_fix_cnt<<<1, 32>>>();

    dim3 g1(I / 256, M / 128);            // 56 x 64
    upgate_mma<<<g1, 256, SMEM_UP>>>(mx, mu, mg, x, wg, wu, avg, M, H, I);

    fix_mask_kernel<<<1024, 256>>>(x, wg, wu, avg, H, I);

    dim3 g2(H / 256, M / 128);            // 16 x 64
    down_mma<<<g2, 256, SMEM_DOWN>>>(mt, mw, wd, out, M, H, I);
}